// round 11
// baseline (speedup 1.0000x reference)
#include <cuda_runtime.h>
#include <cstdint>

#define NN    10000
#define EE    160000
#define INDIM 1000
#define HID   256
#define OUTD  2
#define KP    1008          // 63 * 16, zero-padded K
#define NCH   63

// ---------------- scratch (static __device__, no runtime alloc) ----------------
__device__ float g_xw1[NN * HID];    // features @ W1
__device__ float g_hw2[NN * OUTD];   // relu(gcn1) @ W2
__device__ float g_featp[NN * KP];   // tf32-rounded, k-permuted, padded features (40.3MB)
__device__ float g_w1p[HID * KP];    // tf32-rounded, transposed, k-permuted W1 (1MB)
__device__ float g_dinv[NN];
__device__ float g_sq[NN];
__device__ int   g_deg[NN];
__device__ int   g_cur[NN];
__device__ int   g_off[NN + 1];
__device__ int   g_srcv[EE];

// ================= helpers =================
__device__ __forceinline__ uint32_t smem_u32(const void* p) {
    uint32_t a;
    asm("{ .reg .u64 t; cvta.to.shared.u64 t, %1; cvt.u32.u64 %0, t; }"
        : "=r"(a) : "l"(p));
    return a;
}

__device__ __forceinline__ void cp16(uint32_t dst, const void* src, int sz) {
    asm volatile("cp.async.cg.shared.global [%0], [%1], 16, %2;"
                 :: "r"(dst), "l"(src), "r"(sz) : "memory");
}

__device__ __forceinline__ float tf32f(float x) {
    uint32_t u;
    asm("cvt.rna.tf32.f32 %0, %1;" : "=r"(u) : "f"(x));
    return __uint_as_float(u);
}

__device__ __forceinline__ void mma_tf32(float* d, const uint32_t* a, const uint32_t* b) {
    asm volatile(
        "mma.sync.aligned.m16n8k8.row.col.f32.tf32.tf32.f32 "
        "{%0,%1,%2,%3}, {%4,%5,%6,%7}, {%8,%9}, {%0,%1,%2,%3};"
        : "+f"(d[0]), "+f"(d[1]), "+f"(d[2]), "+f"(d[3])
        : "r"(a[0]), "r"(a[1]), "r"(a[2]), "r"(a[3]), "r"(b[0]), "r"(b[1]));
}

#define F2U __float_as_uint

// ---------------- prep A: features -> g_featp (round + pad + per-16 k-perm) ----------------
// out[m][16c + k'] = tf32(features[m][16c + kl]), k' = (kl%4)*4 + kl/4 (self-inverse)
// out float4 j' = transpose of the 4 input float4s: {in0[j'], in1[j'], in2[j'], in3[j']}
__global__ void k_prepA(const float* __restrict__ f) {
    int gidx = blockIdx.x * blockDim.x + threadIdx.x;     // one 16-float group
    if (gidx >= NN * NCH) return;
    int m = gidx / NCH, c = gidx % NCH;
    const float* src = f + (size_t)m * INDIM + c * 16;
    float4 in[4];
#pragma unroll
    for (int j = 0; j < 4; j++) {
        int k = c * 16 + j * 4;
        if (k + 4 <= INDIM) {
            float4 v = *(const float4*)(src + j * 4);
            in[j] = make_float4(tf32f(v.x), tf32f(v.y), tf32f(v.z), tf32f(v.w));
        } else {
            in[j] = make_float4(0.f, 0.f, 0.f, 0.f);
        }
    }
    float4* dst = (float4*)(g_featp + (size_t)m * KP + c * 16);
    dst[0] = make_float4(in[0].x, in[1].x, in[2].x, in[3].x);
    dst[1] = make_float4(in[0].y, in[1].y, in[2].y, in[3].y);
    dst[2] = make_float4(in[0].z, in[1].z, in[2].z, in[3].z);
    dst[3] = make_float4(in[0].w, in[1].w, in[2].w, in[3].w);
}

// ---------------- prep W: W1[k][n] -> g_w1p[n][16c + k'] (transpose + round + pad + perm) ----------------
__global__ void k_prepW(const float* __restrict__ W1) {
    int gidx = blockIdx.x * blockDim.x + threadIdx.x;     // g = c*HID + n (coalesced reads)
    if (gidx >= HID * NCH) return;
    int c = gidx / HID, n = gidx % HID;
    float out[16];
#pragma unroll
    for (int kl = 0; kl < 16; kl++) {
        int k = c * 16 + kl;
        int kp = (kl & 3) * 4 + (kl >> 2);
        out[kp] = (k < INDIM) ? tf32f(W1[(size_t)k * HID + n]) : 0.f;
    }
    float* dst = g_w1p + (size_t)n * KP + c * 16;
#pragma unroll
    for (int kl = 0; kl < 16; kl++) dst[kl] = out[kl];
}

// ---------------- CSR build ----------------
__global__ void k_zero_deg() {
    int i = blockIdx.x * blockDim.x + threadIdx.x;
    if (i < NN) g_deg[i] = 0;
}

__global__ void k_count(const int* __restrict__ ei) {
    int i = blockIdx.x * blockDim.x + threadIdx.x;
    if (i < EE / 4) {
        int4 d = ((const int4*)(ei + EE))[i];
        atomicAdd(&g_deg[d.x], 1);
        atomicAdd(&g_deg[d.y], 1);
        atomicAdd(&g_deg[d.z], 1);
        atomicAdd(&g_deg[d.w], 1);
    }
}

__global__ void k_scan() {
    __shared__ int part[256];
    __shared__ int excl[257];
    int t = threadIdx.x;
    const int CH = (NN + 255) / 256;
    int base = t * CH;
    int s = 0;
    for (int i = 0; i < CH; i++) {
        int idx = base + i;
        if (idx < NN) s += g_deg[idx];
    }
    part[t] = s;
    __syncthreads();
    if (t == 0) {
        int run = 0;
        for (int i = 0; i < 256; i++) { excl[i] = run; run += part[i]; }
        excl[256] = run;
    }
    __syncthreads();
    int off = excl[t];
    for (int i = 0; i < CH; i++) {
        int idx = base + i;
        if (idx < NN) {
            g_off[idx] = off;
            g_cur[idx] = off;
            int d = g_deg[idx];
            off += d;
            g_dinv[idx] = rsqrtf((float)(d + 1));
        }
    }
    if (t == 255) g_off[NN] = excl[256];
}

__global__ void k_scatter(const int* __restrict__ ei) {
    int i = blockIdx.x * blockDim.x + threadIdx.x;
    if (i < EE / 4) {
        int4 sv = ((const int4*)ei)[i];
        int4 dv = ((const int4*)(ei + EE))[i];
        g_srcv[atomicAdd(&g_cur[dv.x], 1)] = sv.x;
        g_srcv[atomicAdd(&g_cur[dv.y], 1)] = sv.y;
        g_srcv[atomicAdd(&g_cur[dv.z], 1)] = sv.z;
        g_srcv[atomicAdd(&g_cur[dv.w], 1)] = sv.w;
    }
}

// ---------------- GEMM1: g_featp[10000,1008p] @ g_w1p -> g_xw1 ----------------
// CTA tile M=64, N=128, K=16/chunk, 3-stage cp.async. 256 thr, warps 2M x 4N.
// SMEM: per stage A 64x16f (4KB) + B 128x16f (8KB); rows 64B -> LDS.128 conflict-free.
#define ASTG_F 1024                    // floats
#define BSTG_F 2048
#define STG_F  (ASTG_F + BSTG_F)       // 3072 floats = 12KB
#define STG_B  (STG_F * 4)

__global__ __launch_bounds__(256) void k_gemm_mma() {
    __shared__ __align__(16) float sm[3 * STG_F];  // 36KB
    int tid = threadIdx.x;
    int warp = tid >> 5, lane = tid & 31;
    int g = lane >> 2, tig = lane & 3;
    int wm = (warp >> 2) * 32;       // 0 or 32
    int wn = (warp & 3) * 32;        // 0..96
    int ctaRow0 = blockIdx.y * 64;
    int n0 = blockIdx.x * 128;

    // ---- load state (chunk-invariant) ----
    int arow = tid >> 2, aseg = tid & 3;
    const float* aSrc = g_featp + (size_t)(ctaRow0 + arow) * KP + aseg * 4;
    uint32_t aDst = smem_u32(sm) + arow * 64 + aseg * 16;
    int szA = (ctaRow0 + arow < NN) ? 16 : 0;

    int brow0 = tid >> 2, bseg = tid & 3;            // rows 0..63
    int brow1 = brow0 + 64;                          // rows 64..127
    const float* bSrc0 = g_w1p + (size_t)(n0 + brow0) * KP + bseg * 4;
    const float* bSrc1 = g_w1p + (size_t)(n0 + brow1) * KP + bseg * 4;
    uint32_t bDst0 = smem_u32(sm) + 4096 + brow0 * 64 + bseg * 16;
    uint32_t bDst1 = smem_u32(sm) + 4096 + brow1 * 64 + bseg * 16;

    uint32_t ldOff = 0;

    // fragment float4 bases (stage 0): index = row*4 + tig
    const float4* aF0 = (const float4*)sm + (wm + g) * 4 + tig;
    const float4* bF0 = (const float4*)(sm + ASTG_F) + (wn + g) * 4 + tig;

    float d[2][4][4];
#pragma unroll
    for (int mt = 0; mt < 2; mt++)
#pragma unroll
        for (int nt = 0; nt < 4; nt++)
#pragma unroll
            for (int r = 0; r < 4; r++) d[mt][nt][r] = 0.0f;

    // ---- prologue: chunks 0,1 ----
#pragma unroll
    for (int pc = 0; pc < 2; pc++) {
        cp16(aDst + ldOff, aSrc, szA);
        cp16(bDst0 + ldOff, bSrc0, 16);
        cp16(bDst1 + ldOff, bSrc1, 16);
        asm volatile("cp.async.commit_group;" ::: "memory");
        aSrc += 16; bSrc0 += 16; bSrc1 += 16;
        ldOff += STG_B;
    }

    int csOff = 0;   // float4 stage offset for compute
    for (int c = 0; c < NCH; c++) {
        asm volatile("cp.async.wait_group 1;" ::: "memory");
        __syncthreads();
        if (c + 2 < NCH) {
            cp16(aDst + ldOff, aSrc, szA);
            cp16(bDst0 + ldOff, bSrc0, 16);
            cp16(bDst1 + ldOff, bSrc1, 16);
            aSrc += 16; bSrc0 += 16; bSrc1 += 16;
            ldOff += STG_B;
            if (ldOff == 3 * STG_B) ldOff = 0;
        }
        asm volatile("cp.async.commit_group;" ::: "memory");

        const float4* aF = aF0 + csOff;
        const float4* bF = bF0 + csOff;
        csOff += STG_F / 4;
        if (csOff == 3 * (STG_F / 4)) csOff = 0;

        // 8 LDS.128: av[mi] covers m = wm+mi*8+g, k' group tig -> k = {tig, tig+4, tig+8, tig+12}
        float4 av[4], bv[4];
#pragma unroll
        for (int mi = 0; mi < 4; mi++) av[mi] = aF[mi * 32];
#pragma unroll
        for (int ni = 0; ni < 4; ni++) bv[ni] = bF[ni * 32];

        uint32_t a00[4] = {F2U(av[0].x), F2U(av[1].x), F2U(av[0].y), F2U(av[1].y)};  // ks0 mt0
        uint32_t a01[4] = {F2U(av[2].x), F2U(av[3].x), F2U(av[2].y), F2U(av[3].y)};  // ks0 mt1
        uint32_t a10[4] = {F2U(av[0].z), F2U(av[1].z), F2U(av[0].w), F2U(av[1].w)};  // ks1 mt0
        uint32_t a11[4] = {F2U(av[2].z), F2U(av[3].z), F2U(av[2].w), F2U(av[3].w)};  // ks1 mt1
#pragma unroll
        for (int nt = 0; nt < 4; nt++) {
            uint32_t b0[2] = {F2U(bv[nt].x), F2U(bv[nt].y)};   // ks0
            uint32_t b1[2] = {F2U(bv[nt].z), F2U(bv[nt].w)};   // ks1
            mma_tf32(d[0][nt], a00, b0);
            mma_tf32(d[1][nt], a01, b0);
            mma_tf32(d[0][nt], a10, b1);
            mma_tf32(d[1][nt], a11, b1);
        }
    }

#pragma unroll
    for (int mt = 0; mt < 2; mt++) {
        int row0 = ctaRow0 + wm + mt * 16 + g;
#pragma unroll
        for (int nt = 0; nt < 4; nt++) {
            int col = n0 + wn + nt * 8 + 2 * tig;
            if (row0 < NN)
                *(float2*)&g_xw1[(size_t)row0 * HID + col] =
                    make_float2(d[mt][nt][0], d[mt][nt][1]);
            if (row0 + 8 < NN)
                *(float2*)&g_xw1[(size_t)(row0 + 8) * HID + col] =
                    make_float2(d[mt][nt][2], d[mt][nt][3]);
        }
    }
}

// ---------------- fused agg1 + bias + relu + W2 projection -> g_hw2 ----------------
__global__ void k_agg1(const float* __restrict__ b1, const float* __restrict__ W2) {
    int w = (blockIdx.x * blockDim.x + threadIdx.x) >> 5;
    int lane = threadIdx.x & 31;
    if (w >= NN) return;
    float di = g_dinv[w];
    float acc[8];
    const float* xi = g_xw1 + (size_t)w * HID;
#pragma unroll
    for (int u = 0; u < 8; u++) acc[u] = di * xi[u * 32 + lane];
    int p0 = g_off[w], p1 = g_off[w + 1];
    for (int p = p0; p < p1; p++) {
        int s = g_srcv[p];
        float ds = g_dinv[s];
        const float* xs = g_xw1 + (size_t)s * HID;
#pragma unroll
        for (int u = 0; u < 8; u++) acc[u] = fmaf(ds, xs[u * 32 + lane], acc[u]);
    }
    float a0 = 0.f, a1 = 0.f;
#pragma unroll
    for (int u = 0; u < 8; u++) {
        int f = u * 32 + lane;
        float h = fmaxf(fmaf(di, acc[u], b1[f]), 0.0f);
        a0 = fmaf(h, W2[f * 2 + 0], a0);
        a1 = fmaf(h, W2[f * 2 + 1], a1);
    }
#pragma unroll
    for (int o = 16; o > 0; o >>= 1) {
        a0 += __shfl_down_sync(0xffffffffu, a0, o);
        a1 += __shfl_down_sync(0xffffffffu, a1, o);
    }
    if (lane == 0) {
        g_hw2[w * 2 + 0] = a0;
        g_hw2[w * 2 + 1] = a1;
    }
}

// ---------------- agg2 + bias -> emb (d_out) and sq ----------------
__global__ void k_agg2(const float* __restrict__ b2, float* __restrict__ emb) {
    int i = blockIdx.x * blockDim.x + threadIdx.x;
    if (i >= NN) return;
    float di = g_dinv[i];
    float a0 = di * g_hw2[i * 2 + 0];
    float a1 = di * g_hw2[i * 2 + 1];
    int p0 = g_off[i], p1 = g_off[i + 1];
    for (int p = p0; p < p1; p++) {
        int s = g_srcv[p];
        float ds = g_dinv[s];
        a0 = fmaf(ds, g_hw2[s * 2 + 0], a0);
        a1 = fmaf(ds, g_hw2[s * 2 + 1], a1);
    }
    float e0 = fmaf(di, a0, b2[0]);
    float e1 = fmaf(di, a1, b2[1]);
    emb[i * 2 + 0] = e0;
    emb[i * 2 + 1] = e1;
    g_sq[i] = e0 * e0 + e1 * e1;
}

// ---------------- q matrix: q = 1/(1 + 0.5*dist), streaming float4 stores ----------------
#define TJ 1024
#define TI 16

__device__ __forceinline__ float qval(float d2) {
    float d2c = fmaxf(d2, 1e-30f);
    float dist = d2c * rsqrtf(d2c);
    return __fdividef(1.0f, fmaf(0.5f, dist, 1.0f));
}

__global__ __launch_bounds__(256) void k_q(const float* __restrict__ emb,
                                           float* __restrict__ q) {
    __shared__ float sx[TJ], sy[TJ], ss[TJ];
    int j0 = blockIdx.x * TJ;
    int i0 = blockIdx.y * TI;
    int t = threadIdx.x;
#pragma unroll
    for (int v = 0; v < 4; v++) {
        int jl = t + v * 256;
        int jj = j0 + jl;
        if (jj < NN) {
            sx[jl] = emb[jj * 2 + 0];
            sy[jl] = emb[jj * 2 + 1];
            ss[jl] = g_sq[jj];
        }
    }
    __syncthreads();
    int jl = t * 4;
    int j = j0 + jl;
    if (j >= NN) return;
    float x0 = sx[jl], x1 = sx[jl + 1], x2 = sx[jl + 2], x3 = sx[jl + 3];
    float y0 = sy[jl], y1 = sy[jl + 1], y2 = sy[jl + 2], y3 = sy[jl + 3];
    float s0 = ss[jl], s1 = ss[jl + 1], s2 = ss[jl + 2], s3 = ss[jl + 3];
#pragma unroll
    for (int r = 0; r < TI; r++) {
        int i = i0 + r;
        float ex = emb[i * 2 + 0];
        float ey = emb[i * 2 + 1];
        float si = g_sq[i];
        float4 o;
        o.x = qval(si + s0 - 2.0f * fmaf(ex, x0, ey * y0));
        o.y = qval(si + s1 - 2.0f * fmaf(ex, x1, ey * y1));
        o.z = qval(si + s2 - 2.0f * fmaf(ex, x2, ey * y2));
        o.w = qval(si + s3 - 2.0f * fmaf(ex, x3, ey * y3));
        __stcs((float4*)(q + (size_t)i * NN + j), o);
    }
}

// ---------------- launch ----------------
extern "C" void kernel_launch(void* const* d_in, const int* in_sizes, int n_in,
                              void* d_out, int out_size) {
    const float* features = (const float*)d_in[0];
    const int*   ei       = (const int*)d_in[1];
    const float* W1       = (const float*)d_in[2];
    const float* b1       = (const float*)d_in[3];
    const float* W2       = (const float*)d_in[4];
    const float* b2       = (const float*)d_in[5];
    float* out = (float*)d_out;
    float* emb = out;                 // [NN, 2]
    float* q   = out + NN * OUTD;     // [NN, NN]

    k_prepW<<<(HID * NCH + 255) / 256, 256>>>(W1);           // 0
    k_prepA<<<(NN * NCH + 255) / 256, 256>>>(features);      // 1
    k_zero_deg<<<(NN + 255) / 256, 256>>>();                 // 2

    dim3 gg(HID / 128, (NN + 63) / 64);  // (2, 157) = 314 CTAs
    k_gemm_mma<<<gg, 256>>>();                               // 3 (profiled slot)

    k_count<<<(EE / 4 + 255) / 256, 256>>>(ei);              // 4
    k_scan<<<1, 256>>>();                                    // 5
    k_scatter<<<(EE / 4 + 255) / 256, 256>>>(ei);            // 6
    k_agg1<<<(NN * 32 + 255) / 256, 256>>>(b1, W2);          // 7
    k_agg2<<<(NN + 255) / 256, 256>>>(b2, emb);              // 8

    dim3 gq((NN + TJ - 1) / TJ, NN / TI);
    k_q<<<gq, 256>>>(emb, q);                                // 9
}

// round 13
// speedup vs baseline: 1.4775x; 1.4775x over previous
#include <cuda_runtime.h>
#include <cstdint>

#define NN    10000
#define EE    160000
#define INDIM 1000
#define HID   256
#define OUTD  2

// ---------------- scratch (static __device__, no runtime alloc) ----------------
__device__ float g_xw1[NN * HID];    // features @ W1
__device__ float g_hw2[NN * OUTD];   // relu(gcn1) @ W2
__device__ float g_w1r[INDIM * HID]; // rna-tf32-rounded W1 (1MB, L2-resident)
__device__ float g_dinv[NN];
__device__ float g_sq[NN];
__device__ int   g_deg[NN];          // zero-init; k_scan re-zeroes after use
__device__ int   g_cur[NN];
__device__ int   g_off[NN + 1];
__device__ int   g_srcv[EE];

// ================= helpers =================
__device__ __forceinline__ uint32_t smem_u32(const void* p) {
    uint32_t a;
    asm("{ .reg .u64 t; cvta.to.shared.u64 t, %1; cvt.u32.u64 %0, t; }"
        : "=r"(a) : "l"(p));
    return a;
}

__device__ __forceinline__ void cp16(uint32_t dst, const void* src, int sz) {
    asm volatile("cp.async.cg.shared.global [%0], [%1], 16, %2;"
                 :: "r"(dst), "l"(src), "r"(sz) : "memory");
}

__device__ __forceinline__ uint32_t tf32r(float x) {
    uint32_t u;
    asm("cvt.rna.tf32.f32 %0, %1;" : "=r"(u) : "f"(x));
    return u;
}

__device__ __forceinline__ void mma_tf32(float* d, const uint32_t* a, const uint32_t* b) {
    asm volatile(
        "mma.sync.aligned.m16n8k8.row.col.f32.tf32.tf32.f32 "
        "{%0,%1,%2,%3}, {%4,%5,%6,%7}, {%8,%9}, {%0,%1,%2,%3};"
        : "+f"(d[0]), "+f"(d[1]), "+f"(d[2]), "+f"(d[3])
        : "r"(a[0]), "r"(a[1]), "r"(a[2]), "r"(a[3]), "r"(b[0]), "r"(b[1]));
}

// ---------------- W1 pre-round (fp32 -> nearest tf32) ----------------
__global__ void k_roundW(const float* __restrict__ W1) {
    int i = blockIdx.x * blockDim.x + threadIdx.x;
    if (i < INDIM * HID / 4) {
        float4 v = ((const float4*)W1)[i];
        v.x = __uint_as_float(tf32r(v.x));
        v.y = __uint_as_float(tf32r(v.y));
        v.z = __uint_as_float(tf32r(v.z));
        v.w = __uint_as_float(tf32r(v.w));
        ((float4*)g_w1r)[i] = v;
    }
}

// ---------------- CSR build ----------------
__global__ void k_count(const int* __restrict__ ei) {
    int i = blockIdx.x * blockDim.x + threadIdx.x;
    if (i < EE / 4) {
        int4 d = ((const int4*)(ei + EE))[i];
        atomicAdd(&g_deg[d.x], 1);
        atomicAdd(&g_deg[d.y], 1);
        atomicAdd(&g_deg[d.z], 1);
        atomicAdd(&g_deg[d.w], 1);
    }
}

// single-block scan; also zeroes g_deg after reading (restores state for graph replay)
__global__ void k_scan() {
    __shared__ int part[256];
    __shared__ int excl[257];
    int t = threadIdx.x;
    const int CH = (NN + 255) / 256;
    int base = t * CH;
    int s = 0;
    for (int i = 0; i < CH; i++) {
        int idx = base + i;
        if (idx < NN) s += g_deg[idx];
    }
    part[t] = s;
    __syncthreads();
    if (t == 0) {
        int run = 0;
        for (int i = 0; i < 256; i++) { excl[i] = run; run += part[i]; }
        excl[256] = run;
    }
    __syncthreads();
    int off = excl[t];
    for (int i = 0; i < CH; i++) {
        int idx = base + i;
        if (idx < NN) {
            g_off[idx] = off;
            g_cur[idx] = off;
            int d = g_deg[idx];
            g_deg[idx] = 0;                     // restore for next call
            off += d;
            g_dinv[idx] = rsqrtf((float)(d + 1));
        }
    }
    if (t == 255) g_off[NN] = excl[256];
}

__global__ void k_scatter(const int* __restrict__ ei) {
    int i = blockIdx.x * blockDim.x + threadIdx.x;
    if (i < EE / 4) {
        int4 sv = ((const int4*)ei)[i];
        int4 dv = ((const int4*)(ei + EE))[i];
        g_srcv[atomicAdd(&g_cur[dv.x], 1)] = sv.x;
        g_srcv[atomicAdd(&g_cur[dv.y], 1)] = sv.y;
        g_srcv[atomicAdd(&g_cur[dv.z], 1)] = sv.z;
        g_srcv[atomicAdd(&g_cur[dv.w], 1)] = sv.w;
    }
}

// ---------------- GEMM1 via mma.sync tf32: features[10000,1000] @ W1r[1000,256] ----------------
// CTA tile M=64, N=128, K=16/chunk; 3-stage cp.async; 512 thr, 16 warps as 2M x 8N
// (warp tile 32x16). 2 CTAs/SM -> 32 warps/SM for latency hiding.
// NOTE: A-side cp.async must be issued ONLY by threads 0..255 — a cp.async with
// src-size 0 still ZERO-FILLS its 16B destination (R12 bug: upper threads raced
// zero-fills against real loads at aliased addresses).
#define A_STRIDE 20
#define B_STRIDE 136
#define A_FLOATS (64 * A_STRIDE)              // 1280
#define STAGE_F  (A_FLOATS + 16 * B_STRIDE)   // 3456 floats
#define STAGE_B  (STAGE_F * 4)                // bytes
#define NCH      63

__global__ void __launch_bounds__(512, 2) k_gemm_mma(const float* __restrict__ A) {
    __shared__ __align__(16) float sm[3 * STAGE_F];  // 41472 B
    int tid = threadIdx.x;
    int warp = tid >> 5, lane = tid & 31;
    int g = lane >> 2, tig = lane & 3;
    int wm = (warp >> 3) * 32;       // 0 or 32
    int wn = (warp & 7) * 16;        // 0..112
    int ctaRow0 = blockIdx.y * 64;
    int n0 = blockIdx.x * 128;

    // ---- per-thread load state (chunk-invariant) ----
    // A: 256 cp16 (64 rows x 4 segs) -> threads 0..255 ONLY
    int arow = (tid & 255) >> 2, aseg = tid & 3;
    bool doA = tid < 256;
    int agr = ctaRow0 + arow;
    const float* aSrc = A + (size_t)agr * INDIM + aseg * 4;
    uint32_t aDst = smem_u32(sm + arow * A_STRIDE) + aseg * 16;
    int szA_full = (agr < NN) ? 16 : 0;
    int szA_tail = (agr < NN && aseg < 2) ? 16 : 0;  // chunk 62: k=992,996 valid

    // B: 512 cp16 (16 rows x 32 segs) -> all threads, one each
    int brow = tid >> 5, bseg = tid & 31;
    const float* bSrc = g_w1r + (size_t)brow * HID + n0 + bseg * 4;
    uint32_t bDst = smem_u32(sm + A_FLOATS + brow * B_STRIDE) + bseg * 16;
    int szB_tail = (brow < 8) ? 16 : 0;              // chunk 62: rows 8..15 invalid

    uint32_t ldOff = 0;   // rotating stage byte-offset for loads

    // ---- per-thread fragment bases (stage 0) ----
    const float* aFrag0 = sm + (wm + g) * A_STRIDE + tig;
    const float* bFrag0 = sm + A_FLOATS + tig * B_STRIDE + wn + g;

    float d[2][2][4];
#pragma unroll
    for (int mt = 0; mt < 2; mt++)
#pragma unroll
        for (int nt = 0; nt < 2; nt++)
#pragma unroll
            for (int r = 0; r < 4; r++) d[mt][nt][r] = 0.0f;

    // ---- prologue: chunks 0,1 ----
#pragma unroll
    for (int pc = 0; pc < 2; pc++) {
        if (doA) cp16(aDst + ldOff, aSrc, szA_full);
        cp16(bDst + ldOff, bSrc, 16);
        asm volatile("cp.async.commit_group;" ::: "memory");
        aSrc += 16; bSrc += 16 * HID;
        ldOff += STAGE_B;
    }

    int csOff = 0;   // rotating stage float-offset for compute
    for (int c = 0; c < NCH; c++) {
        asm volatile("cp.async.wait_group 1;" ::: "memory");
        __syncthreads();
        if (c + 2 < NCH) {
            int tail = (c + 2 == 62);
            if (doA) cp16(aDst + ldOff, aSrc, tail ? szA_tail : szA_full);
            cp16(bDst + ldOff, bSrc, tail ? szB_tail : 16);
            aSrc += 16; bSrc += 16 * HID;
            ldOff += STAGE_B;
            if (ldOff == 3 * STAGE_B) ldOff = 0;
        }
        asm volatile("cp.async.commit_group;" ::: "memory");

        const float* aF = aFrag0 + csOff;
        const float* bF = bFrag0 + csOff;
        csOff += STAGE_F;
        if (csOff == 3 * STAGE_F) csOff = 0;

        // fragment prefetch (16 A-LDS+cvt, 8 B-LDS), then 8 MMAs
        uint32_t af[2][2][4], bf[2][2][2];
#pragma unroll
        for (int ks = 0; ks < 2; ks++) {
            int kb = ks * 8;
#pragma unroll
            for (int mt = 0; mt < 2; mt++) {
                af[ks][mt][0] = tf32r(aF[mt * 16 * A_STRIDE + kb]);
                af[ks][mt][1] = tf32r(aF[(mt * 16 + 8) * A_STRIDE + kb]);
                af[ks][mt][2] = tf32r(aF[mt * 16 * A_STRIDE + kb + 4]);
                af[ks][mt][3] = tf32r(aF[(mt * 16 + 8) * A_STRIDE + kb + 4]);
            }
#pragma unroll
            for (int nt = 0; nt < 2; nt++) {
                bf[ks][nt][0] = __float_as_uint(bF[kb * B_STRIDE + nt * 8]);
                bf[ks][nt][1] = __float_as_uint(bF[(kb + 4) * B_STRIDE + nt * 8]);
            }
        }
#pragma unroll
        for (int ks = 0; ks < 2; ks++)
#pragma unroll
            for (int mt = 0; mt < 2; mt++)
#pragma unroll
                for (int nt = 0; nt < 2; nt++)
                    mma_tf32(d[mt][nt], af[ks][mt], bf[ks][nt]);
    }

#pragma unroll
    for (int mt = 0; mt < 2; mt++) {
        int row0 = ctaRow0 + wm + mt * 16 + g;
#pragma unroll
        for (int nt = 0; nt < 2; nt++) {
            int col = n0 + wn + nt * 8 + 2 * tig;
            if (row0 < NN)
                *(float2*)&g_xw1[(size_t)row0 * HID + col] =
                    make_float2(d[mt][nt][0], d[mt][nt][1]);
            if (row0 + 8 < NN)
                *(float2*)&g_xw1[(size_t)(row0 + 8) * HID + col] =
                    make_float2(d[mt][nt][2], d[mt][nt][3]);
        }
    }
}

// ---------------- fused agg1 + bias + relu + W2 projection -> g_hw2 ----------------
__global__ void k_agg1(const float* __restrict__ b1, const float* __restrict__ W2) {
    int w = (blockIdx.x * blockDim.x + threadIdx.x) >> 5;
    int lane = threadIdx.x & 31;
    if (w >= NN) return;
    float di = g_dinv[w];
    float acc[8];
    const float* xi = g_xw1 + (size_t)w * HID;
#pragma unroll
    for (int u = 0; u < 8; u++) acc[u] = di * xi[u * 32 + lane];
    int p0 = g_off[w], p1 = g_off[w + 1];
    for (int p = p0; p < p1; p++) {
        int s = g_srcv[p];
        float ds = g_dinv[s];
        const float* xs = g_xw1 + (size_t)s * HID;
#pragma unroll
        for (int u = 0; u < 8; u++) acc[u] = fmaf(ds, xs[u * 32 + lane], acc[u]);
    }
    float a0 = 0.f, a1 = 0.f;
#pragma unroll
    for (int u = 0; u < 8; u++) {
        int f = u * 32 + lane;
        float h = fmaxf(fmaf(di, acc[u], b1[f]), 0.0f);
        a0 = fmaf(h, W2[f * 2 + 0], a0);
        a1 = fmaf(h, W2[f * 2 + 1], a1);
    }
#pragma unroll
    for (int o = 16; o > 0; o >>= 1) {
        a0 += __shfl_down_sync(0xffffffffu, a0, o);
        a1 += __shfl_down_sync(0xffffffffu, a1, o);
    }
    if (lane == 0) {
        g_hw2[w * 2 + 0] = a0;
        g_hw2[w * 2 + 1] = a1;
    }
}

// ---------------- agg2 + bias -> emb (d_out) and sq ----------------
__global__ void k_agg2(const float* __restrict__ b2, float* __restrict__ emb) {
    int i = blockIdx.x * blockDim.x + threadIdx.x;
    if (i >= NN) return;
    float di = g_dinv[i];
    float a0 = di * g_hw2[i * 2 + 0];
    float a1 = di * g_hw2[i * 2 + 1];
    int p0 = g_off[i], p1 = g_off[i + 1];
    for (int p = p0; p < p1; p++) {
        int s = g_srcv[p];
        float ds = g_dinv[s];
        a0 = fmaf(ds, g_hw2[s * 2 + 0], a0);
        a1 = fmaf(ds, g_hw2[s * 2 + 1], a1);
    }
    float e0 = fmaf(di, a0, b2[0]);
    float e1 = fmaf(di, a1, b2[1]);
    emb[i * 2 + 0] = e0;
    emb[i * 2 + 1] = e1;
    g_sq[i] = e0 * e0 + e1 * e1;
}

// ---------------- q matrix: q = 1/(1 + 0.5*dist), streaming float4 stores ----------------
#define TJ 1024
#define TI 16

__device__ __forceinline__ float qval(float d2) {
    float d2c = fmaxf(d2, 1e-30f);
    float dist = d2c * rsqrtf(d2c);
    return __fdividef(1.0f, fmaf(0.5f, dist, 1.0f));
}

__global__ __launch_bounds__(256) void k_q(const float* __restrict__ emb,
                                           float* __restrict__ q) {
    __shared__ float sx[TJ], sy[TJ], ss[TJ];
    int j0 = blockIdx.x * TJ;
    int i0 = blockIdx.y * TI;
    int t = threadIdx.x;
#pragma unroll
    for (int v = 0; v < 4; v++) {
        int jl = t + v * 256;
        int jj = j0 + jl;
        if (jj < NN) {
            sx[jl] = emb[jj * 2 + 0];
            sy[jl] = emb[jj * 2 + 1];
            ss[jl] = g_sq[jj];
        }
    }
    __syncthreads();
    int jl = t * 4;
    int j = j0 + jl;
    if (j >= NN) return;
    float x0 = sx[jl], x1 = sx[jl + 1], x2 = sx[jl + 2], x3 = sx[jl + 3];
    float y0 = sy[jl], y1 = sy[jl + 1], y2 = sy[jl + 2], y3 = sy[jl + 3];
    float s0 = ss[jl], s1 = ss[jl + 1], s2 = ss[jl + 2], s3 = ss[jl + 3];
#pragma unroll
    for (int r = 0; r < TI; r++) {
        int i = i0 + r;
        float ex = emb[i * 2 + 0];
        float ey = emb[i * 2 + 1];
        float si = g_sq[i];
        float4 o;
        o.x = qval(si + s0 - 2.0f * fmaf(ex, x0, ey * y0));
        o.y = qval(si + s1 - 2.0f * fmaf(ex, x1, ey * y1));
        o.z = qval(si + s2 - 2.0f * fmaf(ex, x2, ey * y2));
        o.w = qval(si + s3 - 2.0f * fmaf(ex, x3, ey * y3));
        __stcs((float4*)(q + (size_t)i * NN + j), o);
    }
}

// ---------------- launch ----------------
extern "C" void kernel_launch(void* const* d_in, const int* in_sizes, int n_in,
                              void* d_out, int out_size) {
    const float* features = (const float*)d_in[0];
    const int*   ei       = (const int*)d_in[1];
    const float* W1       = (const float*)d_in[2];
    const float* b1       = (const float*)d_in[3];
    const float* W2       = (const float*)d_in[4];
    const float* b2       = (const float*)d_in[5];
    float* out = (float*)d_out;
    float* emb = out;                 // [NN, 2]
    float* q   = out + NN * OUTD;     // [NN, NN]

    k_roundW<<<(INDIM * HID / 4 + 255) / 256, 256>>>(W1);    // 0
    k_count<<<(EE / 4 + 255) / 256, 256>>>(ei);              // 1
    k_scan<<<1, 256>>>();                                    // 2

    dim3 gg(HID / 128, (NN + 63) / 64);  // (2, 157) = 314 CTAs
    k_gemm_mma<<<gg, 512>>>(features);                       // 3 (profiled slot)

    k_scatter<<<(EE / 4 + 255) / 256, 256>>>(ei);            // 4
    k_agg1<<<(NN * 32 + 255) / 256, 256>>>(b1, W2);          // 5
    k_agg2<<<(NN + 255) / 256, 256>>>(b2, emb);              // 6

    dim3 gq((NN + TJ - 1) / TJ, NN / TI);
    k_q<<<gq, 256>>>(emb, q);                                // 7
}

// round 14
// speedup vs baseline: 1.6421x; 1.1114x over previous
#include <cuda_runtime.h>
#include <cstdint>

#define NN    10000
#define EE    160000
#define INDIM 1000
#define HID   256
#define OUTD  2

// ---------------- scratch (static __device__, no runtime alloc) ----------------
__device__ float g_xw1[NN * HID];    // features @ W1
__device__ float g_hw2[NN * OUTD];   // relu(gcn1) @ W2
__device__ float g_w1r[INDIM * HID]; // rna-tf32-rounded W1 (1MB, L2-resident)
__device__ float g_dinv[NN];
__device__ float g_sq[NN];
__device__ int   g_deg[NN];          // zero-init; k_scan re-zeroes after use
__device__ int   g_cur[NN];
__device__ int   g_off[NN + 1];
__device__ int   g_srcv[EE];

// ================= helpers =================
__device__ __forceinline__ uint32_t smem_u32(const void* p) {
    uint32_t a;
    asm("{ .reg .u64 t; cvta.to.shared.u64 t, %1; cvt.u32.u64 %0, t; }"
        : "=r"(a) : "l"(p));
    return a;
}

__device__ __forceinline__ void cp16(uint32_t dst, const void* src, int sz) {
    asm volatile("cp.async.cg.shared.global [%0], [%1], 16, %2;"
                 :: "r"(dst), "l"(src), "r"(sz) : "memory");
}

__device__ __forceinline__ uint32_t tf32r(float x) {
    uint32_t u;
    asm("cvt.rna.tf32.f32 %0, %1;" : "=r"(u) : "f"(x));
    return u;
}

__device__ __forceinline__ void mma_tf32(float* d, const uint32_t* a, const uint32_t* b) {
    asm volatile(
        "mma.sync.aligned.m16n8k8.row.col.f32.tf32.tf32.f32 "
        "{%0,%1,%2,%3}, {%4,%5,%6,%7}, {%8,%9}, {%0,%1,%2,%3};"
        : "+f"(d[0]), "+f"(d[1]), "+f"(d[2]), "+f"(d[3])
        : "r"(a[0]), "r"(a[1]), "r"(a[2]), "r"(a[3]), "r"(b[0]), "r"(b[1]));
}

// ---------------- W1 pre-round (fp32 -> nearest tf32) ----------------
__global__ void k_roundW(const float* __restrict__ W1) {
    int i = blockIdx.x * blockDim.x + threadIdx.x;
    if (i < INDIM * HID / 4) {
        float4 v = ((const float4*)W1)[i];
        v.x = __uint_as_float(tf32r(v.x));
        v.y = __uint_as_float(tf32r(v.y));
        v.z = __uint_as_float(tf32r(v.z));
        v.w = __uint_as_float(tf32r(v.w));
        ((float4*)g_w1r)[i] = v;
    }
}

// ---------------- CSR build ----------------
__global__ void k_count(const int* __restrict__ ei) {
    int i = blockIdx.x * blockDim.x + threadIdx.x;
    if (i < EE / 4) {
        int4 d = ((const int4*)(ei + EE))[i];
        atomicAdd(&g_deg[d.x], 1);
        atomicAdd(&g_deg[d.y], 1);
        atomicAdd(&g_deg[d.z], 1);
        atomicAdd(&g_deg[d.w], 1);
    }
}

// single-block scan; also zeroes g_deg after reading (restores state for graph replay)
__global__ void k_scan() {
    __shared__ int part[256];
    __shared__ int excl[257];
    int t = threadIdx.x;
    const int CH = (NN + 255) / 256;
    int base = t * CH;
    int s = 0;
    for (int i = 0; i < CH; i++) {
        int idx = base + i;
        if (idx < NN) s += g_deg[idx];
    }
    part[t] = s;
    __syncthreads();
    if (t == 0) {
        int run = 0;
        for (int i = 0; i < 256; i++) { excl[i] = run; run += part[i]; }
        excl[256] = run;
    }
    __syncthreads();
    int off = excl[t];
    for (int i = 0; i < CH; i++) {
        int idx = base + i;
        if (idx < NN) {
            g_off[idx] = off;
            g_cur[idx] = off;
            int d = g_deg[idx];
            g_deg[idx] = 0;                     // restore for next call
            off += d;
            g_dinv[idx] = rsqrtf((float)(d + 1));
        }
    }
    if (t == 255) g_off[NN] = excl[256];
}

__global__ void k_scatter(const int* __restrict__ ei) {
    int i = blockIdx.x * blockDim.x + threadIdx.x;
    if (i < EE / 4) {
        int4 sv = ((const int4*)ei)[i];
        int4 dv = ((const int4*)(ei + EE))[i];
        g_srcv[atomicAdd(&g_cur[dv.x], 1)] = sv.x;
        g_srcv[atomicAdd(&g_cur[dv.y], 1)] = sv.y;
        g_srcv[atomicAdd(&g_cur[dv.z], 1)] = sv.z;
        g_srcv[atomicAdd(&g_cur[dv.w], 1)] = sv.w;
    }
}

// ---------------- GEMM1 via mma.sync tf32: features[10000,1000] @ W1r[1000,256] ----------------
// CTA tile M=64, N=128, K=32/chunk; 3-stage cp.async (dynamic smem 78KB, 2 CTA/SM);
// 256 thr, warps 2M x 4N (warp tile 32x32) — R10's proven LDS-per-MMA sweet spot.
// K padded to 1024 via cp.async zero-fill; every smem dst uniquely owned per chunk.
#define A_STR2  36
#define A_FL2   (64 * A_STR2)          // 2304 floats
#define B_STR2  136
#define B_FL2   (32 * B_STR2)          // 4352 floats
#define STG2_F  (A_FL2 + B_FL2)        // 6656 floats
#define STG2_B  (STG2_F * 4)           // 26624 bytes
#define GEMM_SMEM (3 * STG2_B)         // 79872 bytes
#define NCH2    32                     // ceil(1000/32)

__global__ void __launch_bounds__(256, 2) k_gemm_mma(const float* __restrict__ A) {
    extern __shared__ __align__(16) float sm[];
    int tid = threadIdx.x;
    int warp = tid >> 5, lane = tid & 31;
    int g = lane >> 2, tig = lane & 3;
    int wm = (warp >> 2) * 32;       // 0 or 32
    int wn = (warp & 3) * 32;        // 0..96
    int ctaRow0 = blockIdx.y * 64;
    int n0 = blockIdx.x * 128;

    // ---- per-thread load state (chunk-invariant) ----
    // A: 512 cp16 (64 rows x 8 segs of 16B) -> 2 per thread
    int aseg = tid & 7;
    const float* aSrc[2];
    uint32_t aDst[2];
    int szAf[2], szAt[2];
#pragma unroll
    for (int j = 0; j < 2; j++) {
        int row = (tid >> 3) + j * 32;
        int gr = ctaRow0 + row;
        aSrc[j] = A + (size_t)gr * INDIM + aseg * 4;
        aDst[j] = smem_u32(sm + row * A_STR2) + aseg * 16;
        szAf[j] = (gr < NN) ? 16 : 0;
        szAt[j] = (gr < NN && aseg < 2) ? 16 : 0;   // chunk 31: k=992..999 valid
    }
    // B: 1024 cp16 (32 k-rows x 32 segs) -> 4 per thread
    int bseg = tid & 31;
    const float* bSrc[4];
    uint32_t bDst[4];
    int szBt[4];
#pragma unroll
    for (int j = 0; j < 4; j++) {
        int row = (tid >> 5) + j * 8;
        bSrc[j] = g_w1r + (size_t)row * HID + n0 + bseg * 4;
        bDst[j] = smem_u32(sm + A_FL2 + row * B_STR2) + bseg * 16;
        szBt[j] = (row < 8) ? 16 : 0;               // chunk 31: k-rows 8..31 invalid
    }

    uint32_t ldOff = 0;   // rotating stage byte-offset for loads

    // ---- per-thread fragment bases (stage 0) ----
    const float* aFrag0 = sm + (wm + g) * A_STR2 + tig;
    const float* bFrag0 = sm + A_FL2 + tig * B_STR2 + wn + g;

    float d[2][4][4];
#pragma unroll
    for (int mt = 0; mt < 2; mt++)
#pragma unroll
        for (int nt = 0; nt < 4; nt++)
#pragma unroll
            for (int r = 0; r < 4; r++) d[mt][nt][r] = 0.0f;

    // ---- prologue: chunks 0,1 ----
#pragma unroll
    for (int pc = 0; pc < 2; pc++) {
#pragma unroll
        for (int j = 0; j < 2; j++) cp16(aDst[j] + ldOff, aSrc[j], szAf[j]);
#pragma unroll
        for (int j = 0; j < 4; j++) cp16(bDst[j] + ldOff, bSrc[j], 16);
        asm volatile("cp.async.commit_group;" ::: "memory");
#pragma unroll
        for (int j = 0; j < 2; j++) aSrc[j] += 32;
#pragma unroll
        for (int j = 0; j < 4; j++) bSrc[j] += 32 * HID;
        ldOff += STG2_B;
    }

    int csOff = 0;   // rotating stage float-offset for compute
    for (int c = 0; c < NCH2; c++) {
        asm volatile("cp.async.wait_group 1;" ::: "memory");
        __syncthreads();
        if (c + 2 < NCH2) {
            bool tail = (c + 2 == NCH2 - 1);
#pragma unroll
            for (int j = 0; j < 2; j++)
                cp16(aDst[j] + ldOff, aSrc[j], tail ? szAt[j] : szAf[j]);
#pragma unroll
            for (int j = 0; j < 4; j++)
                cp16(bDst[j] + ldOff, bSrc[j], tail ? szBt[j] : 16);
#pragma unroll
            for (int j = 0; j < 2; j++) aSrc[j] += 32;
#pragma unroll
            for (int j = 0; j < 4; j++) bSrc[j] += 32 * HID;
            ldOff += STG2_B;
            if (ldOff == 3 * STG2_B) ldOff = 0;
        }
        asm volatile("cp.async.commit_group;" ::: "memory");

        const float* aF = aFrag0 + csOff;
        const float* bF = bFrag0 + csOff;
        csOff += STG2_F;
        if (csOff == 3 * STG2_F) csOff = 0;

        // two half-chunks (kb = 0,8 then 16,24): prefetch frags, then 16 MMAs each
#pragma unroll
        for (int h = 0; h < 2; h++) {
            uint32_t af[2][2][4], bf[2][2][4];   // bf[ks][..] uses [nt][2] packed below
            uint32_t bfr[2][4][2];
#pragma unroll
            for (int ks = 0; ks < 2; ks++) {
                int kb = h * 16 + ks * 8;
#pragma unroll
                for (int mt = 0; mt < 2; mt++) {
                    af[ks][mt][0] = tf32r(aF[(wm ? 0 : 0) + mt * 16 * A_STR2 + kb]);
                    af[ks][mt][1] = tf32r(aF[(mt * 16 + 8) * A_STR2 + kb]);
                    af[ks][mt][2] = tf32r(aF[mt * 16 * A_STR2 + kb + 4]);
                    af[ks][mt][3] = tf32r(aF[(mt * 16 + 8) * A_STR2 + kb + 4]);
                }
#pragma unroll
                for (int nt = 0; nt < 4; nt++) {
                    bfr[ks][nt][0] = __float_as_uint(bF[kb * B_STR2 + nt * 8]);
                    bfr[ks][nt][1] = __float_as_uint(bF[(kb + 4) * B_STR2 + nt * 8]);
                }
            }
#pragma unroll
            for (int ks = 0; ks < 2; ks++)
#pragma unroll
                for (int mt = 0; mt < 2; mt++)
#pragma unroll
                    for (int nt = 0; nt < 4; nt++)
                        mma_tf32(d[mt][nt], af[ks][mt], bfr[ks][nt]);
        }
    }

#pragma unroll
    for (int mt = 0; mt < 2; mt++) {
        int row0 = ctaRow0 + wm + mt * 16 + g;
#pragma unroll
        for (int nt = 0; nt < 4; nt++) {
            int col = n0 + wn + nt * 8 + 2 * tig;
            if (row0 < NN)
                *(float2*)&g_xw1[(size_t)row0 * HID + col] =
                    make_float2(d[mt][nt][0], d[mt][nt][1]);
            if (row0 + 8 < NN)
                *(float2*)&g_xw1[(size_t)(row0 + 8) * HID + col] =
                    make_float2(d[mt][nt][2], d[mt][nt][3]);
        }
    }
}

// ---------------- fused agg1 + bias + relu + W2 projection -> g_hw2 ----------------
__global__ void k_agg1(const float* __restrict__ b1, const float* __restrict__ W2) {
    int w = (blockIdx.x * blockDim.x + threadIdx.x) >> 5;
    int lane = threadIdx.x & 31;
    if (w >= NN) return;
    float di = g_dinv[w];
    float acc[8];
    const float* xi = g_xw1 + (size_t)w * HID;
#pragma unroll
    for (int u = 0; u < 8; u++) acc[u] = di * xi[u * 32 + lane];
    int p0 = g_off[w], p1 = g_off[w + 1];
    for (int p = p0; p < p1; p++) {
        int s = g_srcv[p];
        float ds = g_dinv[s];
        const float* xs = g_xw1 + (size_t)s * HID;
#pragma unroll
        for (int u = 0; u < 8; u++) acc[u] = fmaf(ds, xs[u * 32 + lane], acc[u]);
    }
    float a0 = 0.f, a1 = 0.f;
#pragma unroll
    for (int u = 0; u < 8; u++) {
        int f = u * 32 + lane;
        float h = fmaxf(fmaf(di, acc[u], b1[f]), 0.0f);
        a0 = fmaf(h, W2[f * 2 + 0], a0);
        a1 = fmaf(h, W2[f * 2 + 1], a1);
    }
#pragma unroll
    for (int o = 16; o > 0; o >>= 1) {
        a0 += __shfl_down_sync(0xffffffffu, a0, o);
        a1 += __shfl_down_sync(0xffffffffu, a1, o);
    }
    if (lane == 0) {
        g_hw2[w * 2 + 0] = a0;
        g_hw2[w * 2 + 1] = a1;
    }
}

// ---------------- agg2 + bias -> emb (d_out) and sq ----------------
__global__ void k_agg2(const float* __restrict__ b2, float* __restrict__ emb) {
    int i = blockIdx.x * blockDim.x + threadIdx.x;
    if (i >= NN) return;
    float di = g_dinv[i];
    float a0 = di * g_hw2[i * 2 + 0];
    float a1 = di * g_hw2[i * 2 + 1];
    int p0 = g_off[i], p1 = g_off[i + 1];
    for (int p = p0; p < p1; p++) {
        int s = g_srcv[p];
        float ds = g_dinv[s];
        a0 = fmaf(ds, g_hw2[s * 2 + 0], a0);
        a1 = fmaf(ds, g_hw2[s * 2 + 1], a1);
    }
    float e0 = fmaf(di, a0, b2[0]);
    float e1 = fmaf(di, a1, b2[1]);
    emb[i * 2 + 0] = e0;
    emb[i * 2 + 1] = e1;
    g_sq[i] = e0 * e0 + e1 * e1;
}

// ---------------- q matrix: q = 1/(1 + 0.5*dist), streaming float4 stores ----------------
#define TJ 1024
#define TI 16

__device__ __forceinline__ float qval(float d2) {
    float d2c = fmaxf(d2, 1e-30f);
    float dist = d2c * rsqrtf(d2c);
    return __fdividef(1.0f, fmaf(0.5f, dist, 1.0f));
}

__global__ __launch_bounds__(256) void k_q(const float* __restrict__ emb,
                                           float* __restrict__ q) {
    __shared__ float sx[TJ], sy[TJ], ss[TJ];
    int j0 = blockIdx.x * TJ;
    int i0 = blockIdx.y * TI;
    int t = threadIdx.x;
#pragma unroll
    for (int v = 0; v < 4; v++) {
        int jl = t + v * 256;
        int jj = j0 + jl;
        if (jj < NN) {
            sx[jl] = emb[jj * 2 + 0];
            sy[jl] = emb[jj * 2 + 1];
            ss[jl] = g_sq[jj];
        }
    }
    __syncthreads();
    int jl = t * 4;
    int j = j0 + jl;
    if (j >= NN) return;
    float x0 = sx[jl], x1 = sx[jl + 1], x2 = sx[jl + 2], x3 = sx[jl + 3];
    float y0 = sy[jl], y1 = sy[jl + 1], y2 = sy[jl + 2], y3 = sy[jl + 3];
    float s0 = ss[jl], s1 = ss[jl + 1], s2 = ss[jl + 2], s3 = ss[jl + 3];
#pragma unroll
    for (int r = 0; r < TI; r++) {
        int i = i0 + r;
        float ex = emb[i * 2 + 0];
        float ey = emb[i * 2 + 1];
        float si = g_sq[i];
        float4 o;
        o.x = qval(si + s0 - 2.0f * fmaf(ex, x0, ey * y0));
        o.y = qval(si + s1 - 2.0f * fmaf(ex, x1, ey * y1));
        o.z = qval(si + s2 - 2.0f * fmaf(ex, x2, ey * y2));
        o.w = qval(si + s3 - 2.0f * fmaf(ex, x3, ey * y3));
        __stcs((float4*)(q + (size_t)i * NN + j), o);
    }
}

// ---------------- launch ----------------
extern "C" void kernel_launch(void* const* d_in, const int* in_sizes, int n_in,
                              void* d_out, int out_size) {
    const float* features = (const float*)d_in[0];
    const int*   ei       = (const int*)d_in[1];
    const float* W1       = (const float*)d_in[2];
    const float* b1       = (const float*)d_in[3];
    const float* W2       = (const float*)d_in[4];
    const float* b2       = (const float*)d_in[5];
    float* out = (float*)d_out;
    float* emb = out;                 // [NN, 2]
    float* q   = out + NN * OUTD;     // [NN, NN]

    cudaFuncSetAttribute(k_gemm_mma, cudaFuncAttributeMaxDynamicSharedMemorySize, GEMM_SMEM);

    k_roundW<<<(INDIM * HID / 4 + 255) / 256, 256>>>(W1);    // 0
    k_count<<<(EE / 4 + 255) / 256, 256>>>(ei);              // 1
    k_scan<<<1, 256>>>();                                    // 2

    dim3 gg(HID / 128, (NN + 63) / 64);  // (2, 157) = 314 CTAs
    k_gemm_mma<<<gg, 256, GEMM_SMEM>>>(features);            // 3 (profiled slot)

    k_scatter<<<(EE / 4 + 255) / 256, 256>>>(ei);            // 4
    k_agg1<<<(NN * 32 + 255) / 256, 256>>>(b1, W2);          // 5
    k_agg2<<<(NN + 255) / 256, 256>>>(b2, emb);              // 6

    dim3 gq((NN + TJ - 1) / TJ, NN / TI);
    k_q<<<gq, 256>>>(emb, q);                                // 7
}

// round 15
// speedup vs baseline: 1.8947x; 1.1539x over previous
#include <cuda_runtime.h>
#include <cstdint>

#define NN    10000
#define EE    160000
#define INDIM 1000
#define HID   256
#define OUTD  2

// ---------------- scratch (static __device__, no runtime alloc) ----------------
__device__ float g_xw1[NN * HID];    // features @ W1
__device__ float g_hw2[NN * OUTD];   // relu(gcn1) @ W2
__device__ float g_w1r[INDIM * HID]; // rna-tf32-rounded W1 (1MB, L2-resident)
__device__ float g_dinv[NN];
__device__ float g_sq[NN];
__device__ int   g_deg[NN];          // zero-init; k_scan re-zeroes after use
__device__ int   g_cur[NN];
__device__ int   g_off[NN + 1];
__device__ int   g_srcv[EE];

// ================= helpers =================
__device__ __forceinline__ uint32_t smem_u32(const void* p) {
    uint32_t a;
    asm("{ .reg .u64 t; cvta.to.shared.u64 t, %1; cvt.u32.u64 %0, t; }"
        : "=r"(a) : "l"(p));
    return a;
}

__device__ __forceinline__ void cp16(uint32_t dst, const void* src, int sz) {
    asm volatile("cp.async.cg.shared.global [%0], [%1], 16, %2;"
                 :: "r"(dst), "l"(src), "r"(sz) : "memory");
}

__device__ __forceinline__ uint32_t tf32r(float x) {
    uint32_t u;
    asm("cvt.rna.tf32.f32 %0, %1;" : "=r"(u) : "f"(x));
    return u;
}

__device__ __forceinline__ void mma_tf32(float* d, const uint32_t* a, const uint32_t* b) {
    asm volatile(
        "mma.sync.aligned.m16n8k8.row.col.f32.tf32.tf32.f32 "
        "{%0,%1,%2,%3}, {%4,%5,%6,%7}, {%8,%9}, {%0,%1,%2,%3};"
        : "+f"(d[0]), "+f"(d[1]), "+f"(d[2]), "+f"(d[3])
        : "r"(a[0]), "r"(a[1]), "r"(a[2]), "r"(a[3]), "r"(b[0]), "r"(b[1]));
}

// ---------------- W1 pre-round (fp32 -> nearest tf32) ----------------
__global__ void k_roundW(const float* __restrict__ W1) {
    int i = blockIdx.x * blockDim.x + threadIdx.x;
    if (i < INDIM * HID / 4) {
        float4 v = ((const float4*)W1)[i];
        v.x = __uint_as_float(tf32r(v.x));
        v.y = __uint_as_float(tf32r(v.y));
        v.z = __uint_as_float(tf32r(v.z));
        v.w = __uint_as_float(tf32r(v.w));
        ((float4*)g_w1r)[i] = v;
    }
}

// ---------------- CSR build ----------------
__global__ void k_count(const int* __restrict__ ei) {
    int i = blockIdx.x * blockDim.x + threadIdx.x;
    if (i < EE / 4) {
        int4 d = ((const int4*)(ei + EE))[i];
        atomicAdd(&g_deg[d.x], 1);
        atomicAdd(&g_deg[d.y], 1);
        atomicAdd(&g_deg[d.z], 1);
        atomicAdd(&g_deg[d.w], 1);
    }
}

// single-block scan; also zeroes g_deg after reading (restores state for graph replay)
__global__ void k_scan() {
    __shared__ int part[256];
    __shared__ int excl[257];
    int t = threadIdx.x;
    const int CH = (NN + 255) / 256;
    int base = t * CH;
    int s = 0;
    for (int i = 0; i < CH; i++) {
        int idx = base + i;
        if (idx < NN) s += g_deg[idx];
    }
    part[t] = s;
    __syncthreads();
    if (t == 0) {
        int run = 0;
        for (int i = 0; i < 256; i++) { excl[i] = run; run += part[i]; }
        excl[256] = run;
    }
    __syncthreads();
    int off = excl[t];
    for (int i = 0; i < CH; i++) {
        int idx = base + i;
        if (idx < NN) {
            g_off[idx] = off;
            g_cur[idx] = off;
            int d = g_deg[idx];
            g_deg[idx] = 0;                     // restore for next call
            off += d;
            g_dinv[idx] = rsqrtf((float)(d + 1));
        }
    }
    if (t == 255) g_off[NN] = excl[256];
}

__global__ void k_scatter(const int* __restrict__ ei) {
    int i = blockIdx.x * blockDim.x + threadIdx.x;
    if (i < EE / 4) {
        int4 sv = ((const int4*)ei)[i];
        int4 dv = ((const int4*)(ei + EE))[i];
        g_srcv[atomicAdd(&g_cur[dv.x], 1)] = sv.x;
        g_srcv[atomicAdd(&g_cur[dv.y], 1)] = sv.y;
        g_srcv[atomicAdd(&g_cur[dv.z], 1)] = sv.z;
        g_srcv[atomicAdd(&g_cur[dv.w], 1)] = sv.w;
    }
}

// ---------------- GEMM1 via mma.sync tf32 (R14 champion, unchanged) ----------------
#define A_STR2  36
#define A_FL2   (64 * A_STR2)          // 2304 floats
#define B_STR2  136
#define B_FL2   (32 * B_STR2)          // 4352 floats
#define STG2_F  (A_FL2 + B_FL2)        // 6656 floats
#define STG2_B  (STG2_F * 4)           // 26624 bytes
#define GEMM_SMEM (3 * STG2_B)         // 79872 bytes
#define NCH2    32                     // ceil(1000/32)

__global__ void __launch_bounds__(256, 2) k_gemm_mma(const float* __restrict__ A) {
    extern __shared__ __align__(16) float sm[];
    int tid = threadIdx.x;
    int warp = tid >> 5, lane = tid & 31;
    int g = lane >> 2, tig = lane & 3;
    int wm = (warp >> 2) * 32;
    int wn = (warp & 3) * 32;
    int ctaRow0 = blockIdx.y * 64;
    int n0 = blockIdx.x * 128;

    int aseg = tid & 7;
    const float* aSrc[2];
    uint32_t aDst[2];
    int szAf[2], szAt[2];
#pragma unroll
    for (int j = 0; j < 2; j++) {
        int row = (tid >> 3) + j * 32;
        int gr = ctaRow0 + row;
        aSrc[j] = A + (size_t)gr * INDIM + aseg * 4;
        aDst[j] = smem_u32(sm + row * A_STR2) + aseg * 16;
        szAf[j] = (gr < NN) ? 16 : 0;
        szAt[j] = (gr < NN && aseg < 2) ? 16 : 0;
    }
    int bseg = tid & 31;
    const float* bSrc[4];
    uint32_t bDst[4];
    int szBt[4];
#pragma unroll
    for (int j = 0; j < 4; j++) {
        int row = (tid >> 5) + j * 8;
        bSrc[j] = g_w1r + (size_t)row * HID + n0 + bseg * 4;
        bDst[j] = smem_u32(sm + A_FL2 + row * B_STR2) + bseg * 16;
        szBt[j] = (row < 8) ? 16 : 0;
    }

    uint32_t ldOff = 0;
    const float* aFrag0 = sm + (wm + g) * A_STR2 + tig;
    const float* bFrag0 = sm + A_FL2 + tig * B_STR2 + wn + g;

    float d[2][4][4];
#pragma unroll
    for (int mt = 0; mt < 2; mt++)
#pragma unroll
        for (int nt = 0; nt < 4; nt++)
#pragma unroll
            for (int r = 0; r < 4; r++) d[mt][nt][r] = 0.0f;

#pragma unroll
    for (int pc = 0; pc < 2; pc++) {
#pragma unroll
        for (int j = 0; j < 2; j++) cp16(aDst[j] + ldOff, aSrc[j], szAf[j]);
#pragma unroll
        for (int j = 0; j < 4; j++) cp16(bDst[j] + ldOff, bSrc[j], 16);
        asm volatile("cp.async.commit_group;" ::: "memory");
#pragma unroll
        for (int j = 0; j < 2; j++) aSrc[j] += 32;
#pragma unroll
        for (int j = 0; j < 4; j++) bSrc[j] += 32 * HID;
        ldOff += STG2_B;
    }

    int csOff = 0;
    for (int c = 0; c < NCH2; c++) {
        asm volatile("cp.async.wait_group 1;" ::: "memory");
        __syncthreads();
        if (c + 2 < NCH2) {
            bool tail = (c + 2 == NCH2 - 1);
#pragma unroll
            for (int j = 0; j < 2; j++)
                cp16(aDst[j] + ldOff, aSrc[j], tail ? szAt[j] : szAf[j]);
#pragma unroll
            for (int j = 0; j < 4; j++)
                cp16(bDst[j] + ldOff, bSrc[j], tail ? szBt[j] : 16);
#pragma unroll
            for (int j = 0; j < 2; j++) aSrc[j] += 32;
#pragma unroll
            for (int j = 0; j < 4; j++) bSrc[j] += 32 * HID;
            ldOff += STG2_B;
            if (ldOff == 3 * STG2_B) ldOff = 0;
        }
        asm volatile("cp.async.commit_group;" ::: "memory");

        const float* aF = aFrag0 + csOff;
        const float* bF = bFrag0 + csOff;
        csOff += STG2_F;
        if (csOff == 3 * STG2_F) csOff = 0;

#pragma unroll
        for (int h = 0; h < 2; h++) {
            uint32_t af[2][2][4];
            uint32_t bfr[2][4][2];
#pragma unroll
            for (int ks = 0; ks < 2; ks++) {
                int kb = h * 16 + ks * 8;
#pragma unroll
                for (int mt = 0; mt < 2; mt++) {
                    af[ks][mt][0] = tf32r(aF[mt * 16 * A_STR2 + kb]);
                    af[ks][mt][1] = tf32r(aF[(mt * 16 + 8) * A_STR2 + kb]);
                    af[ks][mt][2] = tf32r(aF[mt * 16 * A_STR2 + kb + 4]);
                    af[ks][mt][3] = tf32r(aF[(mt * 16 + 8) * A_STR2 + kb + 4]);
                }
#pragma unroll
                for (int nt = 0; nt < 4; nt++) {
                    bfr[ks][nt][0] = __float_as_uint(bF[kb * B_STR2 + nt * 8]);
                    bfr[ks][nt][1] = __float_as_uint(bF[(kb + 4) * B_STR2 + nt * 8]);
                }
            }
#pragma unroll
            for (int ks = 0; ks < 2; ks++)
#pragma unroll
                for (int mt = 0; mt < 2; mt++)
#pragma unroll
                    for (int nt = 0; nt < 4; nt++)
                        mma_tf32(d[mt][nt], af[ks][mt], bfr[ks][nt]);
        }
    }

#pragma unroll
    for (int mt = 0; mt < 2; mt++) {
        int row0 = ctaRow0 + wm + mt * 16 + g;
#pragma unroll
        for (int nt = 0; nt < 4; nt++) {
            int col = n0 + wn + nt * 8 + 2 * tig;
            if (row0 < NN)
                *(float2*)&g_xw1[(size_t)row0 * HID + col] =
                    make_float2(d[mt][nt][0], d[mt][nt][1]);
            if (row0 + 8 < NN)
                *(float2*)&g_xw1[(size_t)(row0 + 8) * HID + col] =
                    make_float2(d[mt][nt][2], d[mt][nt][3]);
        }
    }
}

// ---------------- fused agg1 + bias + relu + W2 projection -> g_hw2 ----------------
// lane owns features f = lane*8 .. lane*8+7 -> 2x LDG.128 per neighbor row.
__global__ void k_agg1(const float* __restrict__ b1, const float* __restrict__ W2) {
    int w = (blockIdx.x * blockDim.x + threadIdx.x) >> 5;
    int lane = threadIdx.x & 31;
    if (w >= NN) return;
    float di = g_dinv[w];
    const float4* xi = (const float4*)(g_xw1 + (size_t)w * HID) + lane * 2;
    float4 v0 = xi[0], v1 = xi[1];
    float acc[8];
    acc[0] = di * v0.x; acc[1] = di * v0.y; acc[2] = di * v0.z; acc[3] = di * v0.w;
    acc[4] = di * v1.x; acc[5] = di * v1.y; acc[6] = di * v1.z; acc[7] = di * v1.w;
    int p0 = g_off[w], p1 = g_off[w + 1];
    for (int p = p0; p < p1; p++) {
        int s = g_srcv[p];
        float ds = g_dinv[s];
        const float4* xs = (const float4*)(g_xw1 + (size_t)s * HID) + lane * 2;
        float4 u0 = xs[0], u1 = xs[1];
        acc[0] = fmaf(ds, u0.x, acc[0]); acc[1] = fmaf(ds, u0.y, acc[1]);
        acc[2] = fmaf(ds, u0.z, acc[2]); acc[3] = fmaf(ds, u0.w, acc[3]);
        acc[4] = fmaf(ds, u1.x, acc[4]); acc[5] = fmaf(ds, u1.y, acc[5]);
        acc[6] = fmaf(ds, u1.z, acc[6]); acc[7] = fmaf(ds, u1.w, acc[7]);
    }
    float4 bb0 = ((const float4*)b1)[lane * 2];
    float4 bb1 = ((const float4*)b1)[lane * 2 + 1];
    float bb[8] = {bb0.x, bb0.y, bb0.z, bb0.w, bb1.x, bb1.y, bb1.z, bb1.w};
    float a0 = 0.f, a1 = 0.f;
#pragma unroll
    for (int j = 0; j < 8; j++) {
        int f = lane * 8 + j;
        float h = fmaxf(fmaf(di, acc[j], bb[j]), 0.0f);
        float2 wv = ((const float2*)W2)[f];   // (W2[f][0], W2[f][1]) — 2KB, L1-resident
        a0 = fmaf(h, wv.x, a0);
        a1 = fmaf(h, wv.y, a1);
    }
#pragma unroll
    for (int o = 16; o > 0; o >>= 1) {
        a0 += __shfl_down_sync(0xffffffffu, a0, o);
        a1 += __shfl_down_sync(0xffffffffu, a1, o);
    }
    if (lane == 0) {
        g_hw2[w * 2 + 0] = a0;
        g_hw2[w * 2 + 1] = a1;
    }
}

// ---------------- agg2 + bias -> emb (d_out) and sq ----------------
__global__ void k_agg2(const float* __restrict__ b2, float* __restrict__ emb) {
    int i = blockIdx.x * blockDim.x + threadIdx.x;
    if (i >= NN) return;
    float di = g_dinv[i];
    float a0 = di * g_hw2[i * 2 + 0];
    float a1 = di * g_hw2[i * 2 + 1];
    int p0 = g_off[i], p1 = g_off[i + 1];
    for (int p = p0; p < p1; p++) {
        int s = g_srcv[p];
        float ds = g_dinv[s];
        a0 = fmaf(ds, g_hw2[s * 2 + 0], a0);
        a1 = fmaf(ds, g_hw2[s * 2 + 1], a1);
    }
    float e0 = fmaf(di, a0, b2[0]);
    float e1 = fmaf(di, a1, b2[1]);
    emb[i * 2 + 0] = e0;
    emb[i * 2 + 1] = e1;
    g_sq[i] = e0 * e0 + e1 * e1;
}

// ---------------- q matrix: q = 1/(1 + 0.5*dist), streaming float4 stores ----------------
#define TJ 1024
#define TI 16

__device__ __forceinline__ float qval(float d2) {
    float d2c = fmaxf(d2, 1e-30f);
    float dist = d2c * rsqrtf(d2c);
    return __fdividef(1.0f, fmaf(0.5f, dist, 1.0f));
}

__global__ __launch_bounds__(256) void k_q(const float* __restrict__ emb,
                                           float* __restrict__ q) {
    __shared__ float sx[TJ], sy[TJ], ss[TJ];
    int j0 = blockIdx.x * TJ;
    int i0 = blockIdx.y * TI;
    int t = threadIdx.x;
#pragma unroll
    for (int v = 0; v < 4; v++) {
        int jl = t + v * 256;
        int jj = j0 + jl;
        if (jj < NN) {
            sx[jl] = emb[jj * 2 + 0];
            sy[jl] = emb[jj * 2 + 1];
            ss[jl] = g_sq[jj];
        }
    }
    __syncthreads();
    int jl = t * 4;
    int j = j0 + jl;
    if (j >= NN) return;
    float x0 = sx[jl], x1 = sx[jl + 1], x2 = sx[jl + 2], x3 = sx[jl + 3];
    float y0 = sy[jl], y1 = sy[jl + 1], y2 = sy[jl + 2], y3 = sy[jl + 3];
    float s0 = ss[jl], s1 = ss[jl + 1], s2 = ss[jl + 2], s3 = ss[jl + 3];
#pragma unroll
    for (int r = 0; r < TI; r++) {
        int i = i0 + r;
        float ex = emb[i * 2 + 0];
        float ey = emb[i * 2 + 1];
        float si = g_sq[i];
        float4 o;
        o.x = qval(si + s0 - 2.0f * fmaf(ex, x0, ey * y0));
        o.y = qval(si + s1 - 2.0f * fmaf(ex, x1, ey * y1));
        o.z = qval(si + s2 - 2.0f * fmaf(ex, x2, ey * y2));
        o.w = qval(si + s3 - 2.0f * fmaf(ex, x3, ey * y3));
        __stcs((float4*)(q + (size_t)i * NN + j), o);
    }
}

// ---------------- launch: fork CSR branch onto a second stream ----------------
extern "C" void kernel_launch(void* const* d_in, const int* in_sizes, int n_in,
                              void* d_out, int out_size) {
    const float* features = (const float*)d_in[0];
    const int*   ei       = (const int*)d_in[1];
    const float* W1       = (const float*)d_in[2];
    const float* b1       = (const float*)d_in[3];
    const float* W2       = (const float*)d_in[4];
    const float* b2       = (const float*)d_in[5];
    float* out = (float*)d_out;
    float* emb = out;                 // [NN, 2]
    float* q   = out + NN * OUTD;     // [NN, NN]

    cudaFuncSetAttribute(k_gemm_mma, cudaFuncAttributeMaxDynamicSharedMemorySize, GEMM_SMEM);

    // Try to fork CSR build onto a side stream (captured as a parallel graph
    // branch). Host-side stream/event creation is not timed (only graph replays
    // are). Intentionally not destroyed: destroying a stream that participated
    // in an active capture before EndCapture is illegal; kernel_launch is only
    // called a handful of times (correctness + capture).
    cudaStream_t s1 = 0;
    cudaEvent_t e0 = 0, e1 = 0;
    bool forked =
        cudaStreamCreateWithFlags(&s1, cudaStreamNonBlocking) == cudaSuccess &&
        cudaEventCreateWithFlags(&e0, cudaEventDisableTiming) == cudaSuccess &&
        cudaEventCreateWithFlags(&e1, cudaEventDisableTiming) == cudaSuccess;

    int csrGrid = (EE / 4 + 255) / 256;
    dim3 gg(HID / 128, (NN + 63) / 64);  // (2, 157) = 314 CTAs

    if (forked && cudaEventRecord(e0, 0) == cudaSuccess &&
        cudaStreamWaitEvent(s1, e0, 0) == cudaSuccess) {
        // side branch: CSR build
        k_count<<<csrGrid, 256, 0, s1>>>(ei);
        k_scan<<<1, 256, 0, s1>>>();
        k_scatter<<<csrGrid, 256, 0, s1>>>(ei);
        cudaEventRecord(e1, s1);
        // main branch: weight round + GEMM (overlaps CSR)
        k_roundW<<<(INDIM * HID / 4 + 255) / 256, 256>>>(W1);
        k_gemm_mma<<<gg, 256, GEMM_SMEM>>>(features);
        cudaStreamWaitEvent(0, e1, 0);   // join before agg1
    } else {
        // serial fallback
        k_roundW<<<(INDIM * HID / 4 + 255) / 256, 256>>>(W1);
        k_count<<<csrGrid, 256>>>(ei);
        k_scan<<<1, 256>>>();
        k_gemm_mma<<<gg, 256, GEMM_SMEM>>>(features);
        k_scatter<<<csrGrid, 256>>>(ei);
    }

    k_agg1<<<(NN * 32 + 255) / 256, 256>>>(b1, W2);
    k_agg2<<<(NN + 255) / 256, 256>>>(b2, emb);

    dim3 gq((NN + TJ - 1) / TJ, NN / TI);
    k_q<<<gq, 256>>>(emb, q);
}

// round 16
// speedup vs baseline: 1.9482x; 1.0282x over previous
#include <cuda_runtime.h>
#include <cstdint>

#define NN    10000
#define EE    160000
#define INDIM 1000
#define HID   256
#define OUTD  2

// ---------------- scratch (static __device__, no runtime alloc) ----------------
__device__ float g_xw1[NN * HID];    // features @ W1
__device__ float g_hw2[NN * OUTD];   // relu(gcn1) @ W2
__device__ float g_w1r[INDIM * HID]; // rna-tf32-rounded W1 (1MB, L2-resident)
__device__ float g_dinv[NN];
__device__ float g_sq[NN];
__device__ int   g_deg[NN];          // zero-init; k_scan re-zeroes after use
__device__ int   g_cur[NN];
__device__ int   g_off[NN + 1];
__device__ int   g_srcv[EE];

// ================= helpers =================
__device__ __forceinline__ uint32_t smem_u32(const void* p) {
    uint32_t a;
    asm("{ .reg .u64 t; cvta.to.shared.u64 t, %1; cvt.u32.u64 %0, t; }"
        : "=r"(a) : "l"(p));
    return a;
}

__device__ __forceinline__ void cp16(uint32_t dst, const void* src, int sz) {
    asm volatile("cp.async.cg.shared.global [%0], [%1], 16, %2;"
                 :: "r"(dst), "l"(src), "r"(sz) : "memory");
}

__device__ __forceinline__ uint32_t tf32r(float x) {
    uint32_t u;
    asm("cvt.rna.tf32.f32 %0, %1;" : "=r"(u) : "f"(x));
    return u;
}

__device__ __forceinline__ void mma_tf32(float* d, const uint32_t* a, const uint32_t* b) {
    asm volatile(
        "mma.sync.aligned.m16n8k8.row.col.f32.tf32.tf32.f32 "
        "{%0,%1,%2,%3}, {%4,%5,%6,%7}, {%8,%9}, {%0,%1,%2,%3};"
        : "+f"(d[0]), "+f"(d[1]), "+f"(d[2]), "+f"(d[3])
        : "r"(a[0]), "r"(a[1]), "r"(a[2]), "r"(a[3]), "r"(b[0]), "r"(b[1]));
}

// ---------------- W1 pre-round (fp32 -> nearest tf32) ----------------
__global__ void k_roundW(const float* __restrict__ W1) {
    int i = blockIdx.x * blockDim.x + threadIdx.x;
    if (i < INDIM * HID / 4) {
        float4 v = ((const float4*)W1)[i];
        v.x = __uint_as_float(tf32r(v.x));
        v.y = __uint_as_float(tf32r(v.y));
        v.z = __uint_as_float(tf32r(v.z));
        v.w = __uint_as_float(tf32r(v.w));
        ((float4*)g_w1r)[i] = v;
    }
}

// ---------------- CSR build ----------------
__global__ void k_count(const int* __restrict__ ei) {
    int i = blockIdx.x * blockDim.x + threadIdx.x;
    if (i < EE / 4) {
        int4 d = ((const int4*)(ei + EE))[i];
        atomicAdd(&g_deg[d.x], 1);
        atomicAdd(&g_deg[d.y], 1);
        atomicAdd(&g_deg[d.z], 1);
        atomicAdd(&g_deg[d.w], 1);
    }
}

// single-block scan; also zeroes g_deg after reading (restores state for graph replay)
__global__ void k_scan() {
    __shared__ int part[256];
    __shared__ int excl[257];
    int t = threadIdx.x;
    const int CH = (NN + 255) / 256;
    int base = t * CH;
    int s = 0;
    for (int i = 0; i < CH; i++) {
        int idx = base + i;
        if (idx < NN) s += g_deg[idx];
    }
    part[t] = s;
    __syncthreads();
    if (t == 0) {
        int run = 0;
        for (int i = 0; i < 256; i++) { excl[i] = run; run += part[i]; }
        excl[256] = run;
    }
    __syncthreads();
    int off = excl[t];
    for (int i = 0; i < CH; i++) {
        int idx = base + i;
        if (idx < NN) {
            g_off[idx] = off;
            g_cur[idx] = off;
            int d = g_deg[idx];
            g_deg[idx] = 0;                     // restore for next call
            off += d;
            g_dinv[idx] = rsqrtf((float)(d + 1));
        }
    }
    if (t == 255) g_off[NN] = excl[256];
}

__global__ void k_scatter(const int* __restrict__ ei) {
    int i = blockIdx.x * blockDim.x + threadIdx.x;
    if (i < EE / 4) {
        int4 sv = ((const int4*)ei)[i];
        int4 dv = ((const int4*)(ei + EE))[i];
        g_srcv[atomicAdd(&g_cur[dv.x], 1)] = sv.x;
        g_srcv[atomicAdd(&g_cur[dv.y], 1)] = sv.y;
        g_srcv[atomicAdd(&g_cur[dv.z], 1)] = sv.z;
        g_srcv[atomicAdd(&g_cur[dv.w], 1)] = sv.w;
    }
}

// ---------------- GEMM1 via mma.sync tf32 (R14 champion, unchanged) ----------------
#define A_STR2  36
#define A_FL2   (64 * A_STR2)          // 2304 floats
#define B_STR2  136
#define B_FL2   (32 * B_STR2)          // 4352 floats
#define STG2_F  (A_FL2 + B_FL2)        // 6656 floats
#define STG2_B  (STG2_F * 4)           // 26624 bytes
#define GEMM_SMEM (3 * STG2_B)         // 79872 bytes
#define NCH2    32                     // ceil(1000/32)

__global__ void __launch_bounds__(256, 2) k_gemm_mma(const float* __restrict__ A) {
    extern __shared__ __align__(16) float sm[];
    int tid = threadIdx.x;
    int warp = tid >> 5, lane = tid & 31;
    int g = lane >> 2, tig = lane & 3;
    int wm = (warp >> 2) * 32;
    int wn = (warp & 3) * 32;
    int ctaRow0 = blockIdx.y * 64;
    int n0 = blockIdx.x * 128;

    int aseg = tid & 7;
    const float* aSrc[2];
    uint32_t aDst[2];
    int szAf[2], szAt[2];
#pragma unroll
    for (int j = 0; j < 2; j++) {
        int row = (tid >> 3) + j * 32;
        int gr = ctaRow0 + row;
        aSrc[j] = A + (size_t)gr * INDIM + aseg * 4;
        aDst[j] = smem_u32(sm + row * A_STR2) + aseg * 16;
        szAf[j] = (gr < NN) ? 16 : 0;
        szAt[j] = (gr < NN && aseg < 2) ? 16 : 0;
    }
    int bseg = tid & 31;
    const float* bSrc[4];
    uint32_t bDst[4];
    int szBt[4];
#pragma unroll
    for (int j = 0; j < 4; j++) {
        int row = (tid >> 5) + j * 8;
        bSrc[j] = g_w1r + (size_t)row * HID + n0 + bseg * 4;
        bDst[j] = smem_u32(sm + A_FL2 + row * B_STR2) + bseg * 16;
        szBt[j] = (row < 8) ? 16 : 0;
    }

    uint32_t ldOff = 0;
    const float* aFrag0 = sm + (wm + g) * A_STR2 + tig;
    const float* bFrag0 = sm + A_FL2 + tig * B_STR2 + wn + g;

    float d[2][4][4];
#pragma unroll
    for (int mt = 0; mt < 2; mt++)
#pragma unroll
        for (int nt = 0; nt < 4; nt++)
#pragma unroll
            for (int r = 0; r < 4; r++) d[mt][nt][r] = 0.0f;

#pragma unroll
    for (int pc = 0; pc < 2; pc++) {
#pragma unroll
        for (int j = 0; j < 2; j++) cp16(aDst[j] + ldOff, aSrc[j], szAf[j]);
#pragma unroll
        for (int j = 0; j < 4; j++) cp16(bDst[j] + ldOff, bSrc[j], 16);
        asm volatile("cp.async.commit_group;" ::: "memory");
#pragma unroll
        for (int j = 0; j < 2; j++) aSrc[j] += 32;
#pragma unroll
        for (int j = 0; j < 4; j++) bSrc[j] += 32 * HID;
        ldOff += STG2_B;
    }

    int csOff = 0;
    for (int c = 0; c < NCH2; c++) {
        asm volatile("cp.async.wait_group 1;" ::: "memory");
        __syncthreads();
        if (c + 2 < NCH2) {
            bool tail = (c + 2 == NCH2 - 1);
#pragma unroll
            for (int j = 0; j < 2; j++)
                cp16(aDst[j] + ldOff, aSrc[j], tail ? szAt[j] : szAf[j]);
#pragma unroll
            for (int j = 0; j < 4; j++)
                cp16(bDst[j] + ldOff, bSrc[j], tail ? szBt[j] : 16);
#pragma unroll
            for (int j = 0; j < 2; j++) aSrc[j] += 32;
#pragma unroll
            for (int j = 0; j < 4; j++) bSrc[j] += 32 * HID;
            ldOff += STG2_B;
            if (ldOff == 3 * STG2_B) ldOff = 0;
        }
        asm volatile("cp.async.commit_group;" ::: "memory");

        const float* aF = aFrag0 + csOff;
        const float* bF = bFrag0 + csOff;
        csOff += STG2_F;
        if (csOff == 3 * STG2_F) csOff = 0;

#pragma unroll
        for (int h = 0; h < 2; h++) {
            uint32_t af[2][2][4];
            uint32_t bfr[2][4][2];
#pragma unroll
            for (int ks = 0; ks < 2; ks++) {
                int kb = h * 16 + ks * 8;
#pragma unroll
                for (int mt = 0; mt < 2; mt++) {
                    af[ks][mt][0] = tf32r(aF[mt * 16 * A_STR2 + kb]);
                    af[ks][mt][1] = tf32r(aF[(mt * 16 + 8) * A_STR2 + kb]);
                    af[ks][mt][2] = tf32r(aF[mt * 16 * A_STR2 + kb + 4]);
                    af[ks][mt][3] = tf32r(aF[(mt * 16 + 8) * A_STR2 + kb + 4]);
                }
#pragma unroll
                for (int nt = 0; nt < 4; nt++) {
                    bfr[ks][nt][0] = __float_as_uint(bF[kb * B_STR2 + nt * 8]);
                    bfr[ks][nt][1] = __float_as_uint(bF[(kb + 4) * B_STR2 + nt * 8]);
                }
            }
#pragma unroll
            for (int ks = 0; ks < 2; ks++)
#pragma unroll
                for (int mt = 0; mt < 2; mt++)
#pragma unroll
                    for (int nt = 0; nt < 4; nt++)
                        mma_tf32(d[mt][nt], af[ks][mt], bfr[ks][nt]);
        }
    }

#pragma unroll
    for (int mt = 0; mt < 2; mt++) {
        int row0 = ctaRow0 + wm + mt * 16 + g;
#pragma unroll
        for (int nt = 0; nt < 4; nt++) {
            int col = n0 + wn + nt * 8 + 2 * tig;
            if (row0 < NN)
                *(float2*)&g_xw1[(size_t)row0 * HID + col] =
                    make_float2(d[mt][nt][0], d[mt][nt][1]);
            if (row0 + 8 < NN)
                *(float2*)&g_xw1[(size_t)(row0 + 8) * HID + col] =
                    make_float2(d[mt][nt][2], d[mt][nt][3]);
        }
    }
}

// ---------------- fused agg1 + bias + relu + W2 projection -> g_hw2 ----------------
// Warp per node; lane owns features lane*8..lane*8+7 (2x LDG.128 per row).
// Neighbor loop unrolled x4 with all indices/gathers issued up-front (MLP ~8-10).
__global__ void k_agg1(const float* __restrict__ b1, const float* __restrict__ W2) {
    int w = (blockIdx.x * blockDim.x + threadIdx.x) >> 5;
    int lane = threadIdx.x & 31;
    if (w >= NN) return;
    float di = g_dinv[w];
    const float4* xi = (const float4*)(g_xw1 + (size_t)w * HID) + lane * 2;
    float4 v0 = xi[0], v1 = xi[1];
    float acc[8];
    acc[0] = di * v0.x; acc[1] = di * v0.y; acc[2] = di * v0.z; acc[3] = di * v0.w;
    acc[4] = di * v1.x; acc[5] = di * v1.y; acc[6] = di * v1.z; acc[7] = di * v1.w;
    int p = g_off[w], p1 = g_off[w + 1];

    for (; p + 4 <= p1; p += 4) {
        // issue all independent loads first
        int s0 = g_srcv[p], s1 = g_srcv[p + 1], s2 = g_srcv[p + 2], s3 = g_srcv[p + 3];
        float d0 = g_dinv[s0], d1 = g_dinv[s1], d2 = g_dinv[s2], d3 = g_dinv[s3];
        const float4* x0p = (const float4*)(g_xw1 + (size_t)s0 * HID) + lane * 2;
        const float4* x1p = (const float4*)(g_xw1 + (size_t)s1 * HID) + lane * 2;
        const float4* x2p = (const float4*)(g_xw1 + (size_t)s2 * HID) + lane * 2;
        const float4* x3p = (const float4*)(g_xw1 + (size_t)s3 * HID) + lane * 2;
        float4 a0 = x0p[0], a1 = x0p[1];
        float4 b0 = x1p[0], b1v = x1p[1];
        float4 c0 = x2p[0], c1 = x2p[1];
        float4 e0 = x3p[0], e1 = x3p[1];
        acc[0] = fmaf(d0, a0.x, acc[0]); acc[1] = fmaf(d0, a0.y, acc[1]);
        acc[2] = fmaf(d0, a0.z, acc[2]); acc[3] = fmaf(d0, a0.w, acc[3]);
        acc[4] = fmaf(d0, a1.x, acc[4]); acc[5] = fmaf(d0, a1.y, acc[5]);
        acc[6] = fmaf(d0, a1.z, acc[6]); acc[7] = fmaf(d0, a1.w, acc[7]);
        acc[0] = fmaf(d1, b0.x, acc[0]); acc[1] = fmaf(d1, b0.y, acc[1]);
        acc[2] = fmaf(d1, b0.z, acc[2]); acc[3] = fmaf(d1, b0.w, acc[3]);
        acc[4] = fmaf(d1, b1v.x, acc[4]); acc[5] = fmaf(d1, b1v.y, acc[5]);
        acc[6] = fmaf(d1, b1v.z, acc[6]); acc[7] = fmaf(d1, b1v.w, acc[7]);
        acc[0] = fmaf(d2, c0.x, acc[0]); acc[1] = fmaf(d2, c0.y, acc[1]);
        acc[2] = fmaf(d2, c0.z, acc[2]); acc[3] = fmaf(d2, c0.w, acc[3]);
        acc[4] = fmaf(d2, c1.x, acc[4]); acc[5] = fmaf(d2, c1.y, acc[5]);
        acc[6] = fmaf(d2, c1.z, acc[6]); acc[7] = fmaf(d2, c1.w, acc[7]);
        acc[0] = fmaf(d3, e0.x, acc[0]); acc[1] = fmaf(d3, e0.y, acc[1]);
        acc[2] = fmaf(d3, e0.z, acc[2]); acc[3] = fmaf(d3, e0.w, acc[3]);
        acc[4] = fmaf(d3, e1.x, acc[4]); acc[5] = fmaf(d3, e1.y, acc[5]);
        acc[6] = fmaf(d3, e1.z, acc[6]); acc[7] = fmaf(d3, e1.w, acc[7]);
    }
    for (; p < p1; p++) {
        int s = g_srcv[p];
        float ds = g_dinv[s];
        const float4* xs = (const float4*)(g_xw1 + (size_t)s * HID) + lane * 2;
        float4 u0 = xs[0], u1 = xs[1];
        acc[0] = fmaf(ds, u0.x, acc[0]); acc[1] = fmaf(ds, u0.y, acc[1]);
        acc[2] = fmaf(ds, u0.z, acc[2]); acc[3] = fmaf(ds, u0.w, acc[3]);
        acc[4] = fmaf(ds, u1.x, acc[4]); acc[5] = fmaf(ds, u1.y, acc[5]);
        acc[6] = fmaf(ds, u1.z, acc[6]); acc[7] = fmaf(ds, u1.w, acc[7]);
    }

    float4 bb0 = ((const float4*)b1)[lane * 2];
    float4 bb1 = ((const float4*)b1)[lane * 2 + 1];
    float bb[8] = {bb0.x, bb0.y, bb0.z, bb0.w, bb1.x, bb1.y, bb1.z, bb1.w};
    float a0 = 0.f, a1 = 0.f;
#pragma unroll
    for (int j = 0; j < 8; j++) {
        int f = lane * 8 + j;
        float h = fmaxf(fmaf(di, acc[j], bb[j]), 0.0f);
        float2 wv = ((const float2*)W2)[f];
        a0 = fmaf(h, wv.x, a0);
        a1 = fmaf(h, wv.y, a1);
    }
#pragma unroll
    for (int o = 16; o > 0; o >>= 1) {
        a0 += __shfl_down_sync(0xffffffffu, a0, o);
        a1 += __shfl_down_sync(0xffffffffu, a1, o);
    }
    if (lane == 0) {
        g_hw2[w * 2 + 0] = a0;
        g_hw2[w * 2 + 1] = a1;
    }
}

// ---------------- agg2 + bias -> emb (d_out) and sq (4x unrolled gathers) ----------------
__global__ void k_agg2(const float* __restrict__ b2, float* __restrict__ emb) {
    int i = blockIdx.x * blockDim.x + threadIdx.x;
    if (i >= NN) return;
    float di = g_dinv[i];
    float a0 = di * g_hw2[i * 2 + 0];
    float a1 = di * g_hw2[i * 2 + 1];
    int p = g_off[i], p1 = g_off[i + 1];
    for (; p + 4 <= p1; p += 4) {
        int s0 = g_srcv[p], s1 = g_srcv[p + 1], s2 = g_srcv[p + 2], s3 = g_srcv[p + 3];
        float d0 = g_dinv[s0], d1 = g_dinv[s1], d2 = g_dinv[s2], d3 = g_dinv[s3];
        float2 h0 = *(const float2*)&g_hw2[s0 * 2];
        float2 h1 = *(const float2*)&g_hw2[s1 * 2];
        float2 h2 = *(const float2*)&g_hw2[s2 * 2];
        float2 h3 = *(const float2*)&g_hw2[s3 * 2];
        a0 = fmaf(d0, h0.x, a0); a1 = fmaf(d0, h0.y, a1);
        a0 = fmaf(d1, h1.x, a0); a1 = fmaf(d1, h1.y, a1);
        a0 = fmaf(d2, h2.x, a0); a1 = fmaf(d2, h2.y, a1);
        a0 = fmaf(d3, h3.x, a0); a1 = fmaf(d3, h3.y, a1);
    }
    for (; p < p1; p++) {
        int s = g_srcv[p];
        float ds = g_dinv[s];
        float2 hs = *(const float2*)&g_hw2[s * 2];
        a0 = fmaf(ds, hs.x, a0);
        a1 = fmaf(ds, hs.y, a1);
    }
    float e0 = fmaf(di, a0, b2[0]);
    float e1 = fmaf(di, a1, b2[1]);
    emb[i * 2 + 0] = e0;
    emb[i * 2 + 1] = e1;
    g_sq[i] = e0 * e0 + e1 * e1;
}

// ---------------- q matrix: q = 1/(1 + 0.5*dist), streaming float4 stores ----------------
#define TJ 1024
#define TI 16

__device__ __forceinline__ float qval(float d2) {
    float d2c = fmaxf(d2, 1e-30f);
    float dist = d2c * rsqrtf(d2c);
    return __fdividef(1.0f, fmaf(0.5f, dist, 1.0f));
}

__global__ __launch_bounds__(256) void k_q(const float* __restrict__ emb,
                                           float* __restrict__ q) {
    __shared__ float sx[TJ], sy[TJ], ss[TJ];
    int j0 = blockIdx.x * TJ;
    int i0 = blockIdx.y * TI;
    int t = threadIdx.x;
#pragma unroll
    for (int v = 0; v < 4; v++) {
        int jl = t + v * 256;
        int jj = j0 + jl;
        if (jj < NN) {
            sx[jl] = emb[jj * 2 + 0];
            sy[jl] = emb[jj * 2 + 1];
            ss[jl] = g_sq[jj];
        }
    }
    __syncthreads();
    int jl = t * 4;
    int j = j0 + jl;
    if (j >= NN) return;
    float x0 = sx[jl], x1 = sx[jl + 1], x2 = sx[jl + 2], x3 = sx[jl + 3];
    float y0 = sy[jl], y1 = sy[jl + 1], y2 = sy[jl + 2], y3 = sy[jl + 3];
    float s0 = ss[jl], s1 = ss[jl + 1], s2 = ss[jl + 2], s3 = ss[jl + 3];
#pragma unroll
    for (int r = 0; r < TI; r++) {
        int i = i0 + r;
        float ex = emb[i * 2 + 0];
        float ey = emb[i * 2 + 1];
        float si = g_sq[i];
        float4 o;
        o.x = qval(si + s0 - 2.0f * fmaf(ex, x0, ey * y0));
        o.y = qval(si + s1 - 2.0f * fmaf(ex, x1, ey * y1));
        o.z = qval(si + s2 - 2.0f * fmaf(ex, x2, ey * y2));
        o.w = qval(si + s3 - 2.0f * fmaf(ex, x3, ey * y3));
        __stcs((float4*)(q + (size_t)i * NN + j), o);
    }
}

// ---------------- launch: fork CSR branch onto a second stream ----------------
extern "C" void kernel_launch(void* const* d_in, const int* in_sizes, int n_in,
                              void* d_out, int out_size) {
    const float* features = (const float*)d_in[0];
    const int*   ei       = (const int*)d_in[1];
    const float* W1       = (const float*)d_in[2];
    const float* b1       = (const float*)d_in[3];
    const float* W2       = (const float*)d_in[4];
    const float* b2       = (const float*)d_in[5];
    float* out = (float*)d_out;
    float* emb = out;                 // [NN, 2]
    float* q   = out + NN * OUTD;     // [NN, NN]

    cudaFuncSetAttribute(k_gemm_mma, cudaFuncAttributeMaxDynamicSharedMemorySize, GEMM_SMEM);

    cudaStream_t s1 = 0;
    cudaEvent_t e0 = 0, e1 = 0;
    bool forked =
        cudaStreamCreateWithFlags(&s1, cudaStreamNonBlocking) == cudaSuccess &&
        cudaEventCreateWithFlags(&e0, cudaEventDisableTiming) == cudaSuccess &&
        cudaEventCreateWithFlags(&e1, cudaEventDisableTiming) == cudaSuccess;

    int csrGrid = (EE / 4 + 255) / 256;
    dim3 gg(HID / 128, (NN + 63) / 64);  // (2, 157) = 314 CTAs

    if (forked && cudaEventRecord(e0, 0) == cudaSuccess &&
        cudaStreamWaitEvent(s1, e0, 0) == cudaSuccess) {
        // side branch: CSR build
        k_count<<<csrGrid, 256, 0, s1>>>(ei);
        k_scan<<<1, 256, 0, s1>>>();
        k_scatter<<<csrGrid, 256, 0, s1>>>(ei);
        cudaEventRecord(e1, s1);
        // main branch: weight round + GEMM (overlaps CSR)
        k_roundW<<<(INDIM * HID / 4 + 255) / 256, 256>>>(W1);
        k_gemm_mma<<<gg, 256, GEMM_SMEM>>>(features);
        cudaStreamWaitEvent(0, e1, 0);   // join before agg1
    } else {
        // serial fallback
        k_roundW<<<(INDIM * HID / 4 + 255) / 256, 256>>>(W1);
        k_count<<<csrGrid, 256>>>(ei);
        k_scan<<<1, 256>>>();
        k_gemm_mma<<<gg, 256, GEMM_SMEM>>>(features);
        k_scatter<<<csrGrid, 256>>>(ei);
    }

    k_agg1<<<(NN * 32 + 255) / 256, 256>>>(b1, W2);
    k_agg2<<<(NN + 255) / 256, 256>>>(b2, emb);

    dim3 gq((NN + TJ - 1) / TJ, NN / TI);
    k_q<<<gq, 256>>>(emb, q);
}

// round 17
// speedup vs baseline: 1.9553x; 1.0036x over previous
#include <cuda_runtime.h>
#include <cuda_fp16.h>
#include <cstdint>

#define NN    10000
#define EE    160000
#define INDIM 1000
#define KPAD  1024
#define HID   256
#define OUTD  2

// ---------------- scratch (static __device__, no runtime alloc) ----------------
__device__ float g_xw1[NN * HID];    // features @ W1
__device__ float g_hw2[NN * OUTD];   // relu(gcn1) @ W2
__device__ __half g_ah[NN * KPAD];   // fp16 features, K padded (20.5MB)
__device__ __half g_w1h[HID * KPAD]; // fp16 W1^T, K padded (512KB)
__device__ float g_dinv[NN];
__device__ float g_sq[NN];
__device__ int   g_deg[NN];          // zero-init; k_scan re-zeroes after use
__device__ int   g_cur[NN];
__device__ int   g_off[NN + 1];
__device__ int   g_srcv[EE];

// ================= helpers =================
__device__ __forceinline__ uint32_t smem_u32(const void* p) {
    uint32_t a;
    asm("{ .reg .u64 t; cvta.to.shared.u64 t, %1; cvt.u32.u64 %0, t; }"
        : "=r"(a) : "l"(p));
    return a;
}

__device__ __forceinline__ void cp16(uint32_t dst, const void* src, int sz) {
    asm volatile("cp.async.cg.shared.global [%0], [%1], 16, %2;"
                 :: "r"(dst), "l"(src), "r"(sz) : "memory");
}

__device__ __forceinline__ void mma_f16(float* d, const uint32_t* a, const uint32_t* b) {
    asm volatile(
        "mma.sync.aligned.m16n8k16.row.col.f32.f16.f16.f32 "
        "{%0,%1,%2,%3}, {%4,%5,%6,%7}, {%8,%9}, {%0,%1,%2,%3};"
        : "+f"(d[0]), "+f"(d[1]), "+f"(d[2]), "+f"(d[3])
        : "r"(a[0]), "r"(a[1]), "r"(a[2]), "r"(a[3]), "r"(b[0]), "r"(b[1]));
}

// ---------------- feature fp32 -> fp16 (pad K to 1024) ----------------
// thread = one 16B output group (8 halfs). 1000 = 8*125, groups 125..127 are zero.
__global__ void k_cvtA(const float* __restrict__ f) {
    int idx = blockIdx.x * blockDim.x + threadIdx.x;   // NN*128 total
    int row = idx >> 7, c8 = idx & 127;
    __half2 o[4];
    if (c8 < 125) {
        const float4* src = (const float4*)(f + (size_t)row * INDIM + c8 * 8);
        float4 v0 = src[0], v1 = src[1];
        o[0] = __floats2half2_rn(v0.x, v0.y);
        o[1] = __floats2half2_rn(v0.z, v0.w);
        o[2] = __floats2half2_rn(v1.x, v1.y);
        o[3] = __floats2half2_rn(v1.z, v1.w);
    } else {
        o[0] = o[1] = o[2] = o[3] = __floats2half2_rn(0.f, 0.f);
    }
    *(uint4*)(g_ah + (size_t)row * KPAD + c8 * 8) = *(uint4*)o;
}

// ---------------- W1 [1000,256] -> g_w1h [256][1024] fp16 transposed ----------------
__global__ void k_cvtW(const float* __restrict__ W1) {
    __shared__ __half tile[32][33];
    int kb = blockIdx.x * 32, nb = blockIdx.y * 32;
    int tx = threadIdx.x, ty = threadIdx.y;   // 32 x 8
#pragma unroll
    for (int j = 0; j < 4; j++) {
        int k = kb + ty + j * 8, n = nb + tx;
        tile[ty + j * 8][tx] = (k < INDIM) ? __float2half_rn(W1[(size_t)k * HID + n])
                                           : __half(0.f);
    }
    __syncthreads();
#pragma unroll
    for (int j = 0; j < 4; j++) {
        int n = nb + ty + j * 8, k = kb + tx;
        g_w1h[(size_t)n * KPAD + k] = tile[tx][ty + j * 8];
    }
}

// ---------------- CSR build ----------------
__global__ void k_count(const int* __restrict__ ei) {
    int i = blockIdx.x * blockDim.x + threadIdx.x;
    if (i < EE / 4) {
        int4 d = ((const int4*)(ei + EE))[i];
        atomicAdd(&g_deg[d.x], 1);
        atomicAdd(&g_deg[d.y], 1);
        atomicAdd(&g_deg[d.z], 1);
        atomicAdd(&g_deg[d.w], 1);
    }
}

__global__ void k_scan() {
    __shared__ int part[256];
    __shared__ int excl[257];
    int t = threadIdx.x;
    const int CH = (NN + 255) / 256;
    int base = t * CH;
    int s = 0;
    for (int i = 0; i < CH; i++) {
        int idx = base + i;
        if (idx < NN) s += g_deg[idx];
    }
    part[t] = s;
    __syncthreads();
    if (t == 0) {
        int run = 0;
        for (int i = 0; i < 256; i++) { excl[i] = run; run += part[i]; }
        excl[256] = run;
    }
    __syncthreads();
    int off = excl[t];
    for (int i = 0; i < CH; i++) {
        int idx = base + i;
        if (idx < NN) {
            g_off[idx] = off;
            g_cur[idx] = off;
            int d = g_deg[idx];
            g_deg[idx] = 0;
            off += d;
            g_dinv[idx] = rsqrtf((float)(d + 1));
        }
    }
    if (t == 255) g_off[NN] = excl[256];
}

__global__ void k_scatter(const int* __restrict__ ei) {
    int i = blockIdx.x * blockDim.x + threadIdx.x;
    if (i < EE / 4) {
        int4 sv = ((const int4*)ei)[i];
        int4 dv = ((const int4*)(ei + EE))[i];
        g_srcv[atomicAdd(&g_cur[dv.x], 1)] = sv.x;
        g_srcv[atomicAdd(&g_cur[dv.y], 1)] = sv.y;
        g_srcv[atomicAdd(&g_cur[dv.z], 1)] = sv.z;
        g_srcv[atomicAdd(&g_cur[dv.w], 1)] = sv.w;
    }
}

// ---------------- GEMM1 via mma.sync fp16: g_ah[10000,1024] @ g_w1h^T -> g_xw1 ----------------
// CTA tile M=64, N=128, K=32/chunk; 3-stage cp.async (46KB dynamic, 2 CTA/SM);
// 256 thr, warps 2M x 4N (warp tile 32x32). Smem rows 40 halfs (80B) -> conflict-free.
#define A_STRH  40                     // halfs per A row
#define A_FLH   (64 * A_STRH)          // 2560 halfs
#define B_STRH  40
#define B_FLH   (128 * B_STRH)         // 5120 halfs
#define STGH    (A_FLH + B_FLH)        // 7680 halfs = 15360 B
#define STGB    (STGH * 2)
#define GEMM_SMEM (3 * STGB)           // 46080 B
#define NCHH    32                     // 1024 / 32

__global__ void __launch_bounds__(256, 2) k_gemm_mma() {
    extern __shared__ __align__(16) __half smh[];
    int tid = threadIdx.x;
    int warp = tid >> 5, lane = tid & 31;
    int g = lane >> 2, tig = lane & 3;
    int wm = (warp >> 2) * 32;
    int wn = (warp & 3) * 32;
    int ctaRow0 = blockIdx.y * 64;
    int n0 = blockIdx.x * 128;

    // A: 256 cp16 (64 rows x 4 segs of 8 halfs) -> 1/thread
    int arow = tid >> 2, aseg = tid & 3;
    int agr = ctaRow0 + arow;
    const __half* aSrc = g_ah + (size_t)min(agr, NN - 1) * KPAD + aseg * 8;
    uint32_t aDst = smem_u32(smh + arow * A_STRH) + aseg * 16;
    int szA = (agr < NN) ? 16 : 0;     // zero-fill OK: dst uniquely owned

    // B: 512 cp16 (128 rows x 4 segs) -> 2/thread
    int bseg = tid & 3;
    const __half* bSrc[2];
    uint32_t bDst[2];
#pragma unroll
    for (int j = 0; j < 2; j++) {
        int row = (tid >> 2) + j * 64;
        bSrc[j] = g_w1h + (size_t)(n0 + row) * KPAD + bseg * 8;
        bDst[j] = smem_u32(smh + A_FLH + row * B_STRH) + bseg * 16;
    }

    uint32_t ldOff = 0;
    const __half* aF0 = smh + (wm + g) * A_STRH + 2 * tig;
    const __half* bF0 = smh + A_FLH + (wn + g) * B_STRH + 2 * tig;

    float d[2][4][4];
#pragma unroll
    for (int mt = 0; mt < 2; mt++)
#pragma unroll
        for (int nt = 0; nt < 4; nt++)
#pragma unroll
            for (int r = 0; r < 4; r++) d[mt][nt][r] = 0.0f;

    // prologue: chunks 0,1
#pragma unroll
    for (int pc = 0; pc < 2; pc++) {
        cp16(aDst + ldOff, aSrc, szA);
#pragma unroll
        for (int j = 0; j < 2; j++) cp16(bDst[j] + ldOff, bSrc[j], 16);
        asm volatile("cp.async.commit_group;" ::: "memory");
        aSrc += 32; bSrc[0] += 32; bSrc[1] += 32;
        ldOff += STGB;
    }

    int csOff = 0;   // halfs
    for (int c = 0; c < NCHH; c++) {
        asm volatile("cp.async.wait_group 1;" ::: "memory");
        __syncthreads();
        if (c + 2 < NCHH) {
            cp16(aDst + ldOff, aSrc, szA);
#pragma unroll
            for (int j = 0; j < 2; j++) cp16(bDst[j] + ldOff, bSrc[j], 16);
            aSrc += 32; bSrc[0] += 32; bSrc[1] += 32;
            ldOff += STGB;
            if (ldOff == 3 * STGB) ldOff = 0;
        }
        asm volatile("cp.async.commit_group;" ::: "memory");

        const __half* aF = aF0 + csOff;
        const __half* bF = bF0 + csOff;
        csOff += STGH;
        if (csOff == 3 * STGH) csOff = 0;

#pragma unroll
        for (int ks = 0; ks < 2; ks++) {
            int ko = ks * 16;
            uint32_t af[2][4], bf[4][2];
#pragma unroll
            for (int mt = 0; mt < 2; mt++) {
                const __half* p = aF + mt * 16 * A_STRH + ko;
                af[mt][0] = *(const uint32_t*)(p);
                af[mt][1] = *(const uint32_t*)(p + 8 * A_STRH);
                af[mt][2] = *(const uint32_t*)(p + 8);
                af[mt][3] = *(const uint32_t*)(p + 8 * A_STRH + 8);
            }
#pragma unroll
            for (int nt = 0; nt < 4; nt++) {
                const __half* p = bF + nt * 8 * B_STRH + ko;
                bf[nt][0] = *(const uint32_t*)(p);
                bf[nt][1] = *(const uint32_t*)(p + 8);
            }
#pragma unroll
            for (int mt = 0; mt < 2; mt++)
#pragma unroll
                for (int nt = 0; nt < 4; nt++)
                    mma_f16(d[mt][nt], af[mt], bf[nt]);
        }
    }

#pragma unroll
    for (int mt = 0; mt < 2; mt++) {
        int row0 = ctaRow0 + wm + mt * 16 + g;
#pragma unroll
        for (int nt = 0; nt < 4; nt++) {
            int col = n0 + wn + nt * 8 + 2 * tig;
            if (row0 < NN)
                *(float2*)&g_xw1[(size_t)row0 * HID + col] =
                    make_float2(d[mt][nt][0], d[mt][nt][1]);
            if (row0 + 8 < NN)
                *(float2*)&g_xw1[(size_t)(row0 + 8) * HID + col] =
                    make_float2(d[mt][nt][2], d[mt][nt][3]);
        }
    }
}

// ---------------- fused agg1 + bias + relu + W2 projection -> g_hw2 ----------------
__global__ void k_agg1(const float* __restrict__ b1, const float* __restrict__ W2) {
    int w = (blockIdx.x * blockDim.x + threadIdx.x) >> 5;
    int lane = threadIdx.x & 31;
    if (w >= NN) return;
    float di = g_dinv[w];
    const float4* xi = (const float4*)(g_xw1 + (size_t)w * HID) + lane * 2;
    float4 v0 = xi[0], v1 = xi[1];
    float acc[8];
    acc[0] = di * v0.x; acc[1] = di * v0.y; acc[2] = di * v0.z; acc[3] = di * v0.w;
    acc[4] = di * v1.x; acc[5] = di * v1.y; acc[6] = di * v1.z; acc[7] = di * v1.w;
    int p = g_off[w], p1 = g_off[w + 1];

    for (; p + 4 <= p1; p += 4) {
        int s0 = g_srcv[p], s1 = g_srcv[p + 1], s2 = g_srcv[p + 2], s3 = g_srcv[p + 3];
        float d0 = g_dinv[s0], d1 = g_dinv[s1], d2 = g_dinv[s2], d3 = g_dinv[s3];
        const float4* x0p = (const float4*)(g_xw1 + (size_t)s0 * HID) + lane * 2;
        const float4* x1p = (const float4*)(g_xw1 + (size_t)s1 * HID) + lane * 2;
        const float4* x2p = (const float4*)(g_xw1 + (size_t)s2 * HID) + lane * 2;
        const float4* x3p = (const float4*)(g_xw1 + (size_t)s3 * HID) + lane * 2;
        float4 a0 = x0p[0], a1 = x0p[1];
        float4 b0 = x1p[0], b1v = x1p[1];
        float4 c0 = x2p[0], c1 = x2p[1];
        float4 e0 = x3p[0], e1 = x3p[1];
        acc[0] = fmaf(d0, a0.x, acc[0]); acc[1] = fmaf(d0, a0.y, acc[1]);
        acc[2] = fmaf(d0, a0.z, acc[2]); acc[3] = fmaf(d0, a0.w, acc[3]);
        acc[4] = fmaf(d0, a1.x, acc[4]); acc[5] = fmaf(d0, a1.y, acc[5]);
        acc[6] = fmaf(d0, a1.z, acc[6]); acc[7] = fmaf(d0, a1.w, acc[7]);
        acc[0] = fmaf(d1, b0.x, acc[0]); acc[1] = fmaf(d1, b0.y, acc[1]);
        acc[2] = fmaf(d1, b0.z, acc[2]); acc[3] = fmaf(d1, b0.w, acc[3]);
        acc[4] = fmaf(d1, b1v.x, acc[4]); acc[5] = fmaf(d1, b1v.y, acc[5]);
        acc[6] = fmaf(d1, b1v.z, acc[6]); acc[7] = fmaf(d1, b1v.w, acc[7]);
        acc[0] = fmaf(d2, c0.x, acc[0]); acc[1] = fmaf(d2, c0.y, acc[1]);
        acc[2] = fmaf(d2, c0.z, acc[2]); acc[3] = fmaf(d2, c0.w, acc[3]);
        acc[4] = fmaf(d2, c1.x, acc[4]); acc[5] = fmaf(d2, c1.y, acc[5]);
        acc[6] = fmaf(d2, c1.z, acc[6]); acc[7] = fmaf(d2, c1.w, acc[7]);
        acc[0] = fmaf(d3, e0.x, acc[0]); acc[1] = fmaf(d3, e0.y, acc[1]);
        acc[2] = fmaf(d3, e0.z, acc[2]); acc[3] = fmaf(d3, e0.w, acc[3]);
        acc[4] = fmaf(d3, e1.x, acc[4]); acc[5] = fmaf(d3, e1.y, acc[5]);
        acc[6] = fmaf(d3, e1.z, acc[6]); acc[7] = fmaf(d3, e1.w, acc[7]);
    }
    for (; p < p1; p++) {
        int s = g_srcv[p];
        float ds = g_dinv[s];
        const float4* xs = (const float4*)(g_xw1 + (size_t)s * HID) + lane * 2;
        float4 u0 = xs[0], u1 = xs[1];
        acc[0] = fmaf(ds, u0.x, acc[0]); acc[1] = fmaf(ds, u0.y, acc[1]);
        acc[2] = fmaf(ds, u0.z, acc[2]); acc[3] = fmaf(ds, u0.w, acc[3]);
        acc[4] = fmaf(ds, u1.x, acc[4]); acc[5] = fmaf(ds, u1.y, acc[5]);
        acc[6] = fmaf(ds, u1.z, acc[6]); acc[7] = fmaf(ds, u1.w, acc[7]);
    }

    float4 bb0 = ((const float4*)b1)[lane * 2];
    float4 bb1 = ((const float4*)b1)[lane * 2 + 1];
    float bb[8] = {bb0.x, bb0.y, bb0.z, bb0.w, bb1.x, bb1.y, bb1.z, bb1.w};
    float a0 = 0.f, a1 = 0.f;
#pragma unroll
    for (int j = 0; j < 8; j++) {
        int f = lane * 8 + j;
        float h = fmaxf(fmaf(di, acc[j], bb[j]), 0.0f);
        float2 wv = ((const float2*)W2)[f];
        a0 = fmaf(h, wv.x, a0);
        a1 = fmaf(h, wv.y, a1);
    }
#pragma unroll
    for (int o = 16; o > 0; o >>= 1) {
        a0 += __shfl_down_sync(0xffffffffu, a0, o);
        a1 += __shfl_down_sync(0xffffffffu, a1, o);
    }
    if (lane == 0) {
        g_hw2[w * 2 + 0] = a0;
        g_hw2[w * 2 + 1] = a1;
    }
}

// ---------------- agg2 + bias -> emb (d_out) and sq ----------------
__global__ void k_agg2(const float* __restrict__ b2, float* __restrict__ emb) {
    int i = blockIdx.x * blockDim.x + threadIdx.x;
    if (i >= NN) return;
    float di = g_dinv[i];
    float a0 = di * g_hw2[i * 2 + 0];
    float a1 = di * g_hw2[i * 2 + 1];
    int p = g_off[i], p1 = g_off[i + 1];
    for (; p + 4 <= p1; p += 4) {
        int s0 = g_srcv[p], s1 = g_srcv[p + 1], s2 = g_srcv[p + 2], s3 = g_srcv[p + 3];
        float d0 = g_dinv[s0], d1 = g_dinv[s1], d2 = g_dinv[s2], d3 = g_dinv[s3];
        float2 h0 = *(const float2*)&g_hw2[s0 * 2];
        float2 h1 = *(const float2*)&g_hw2[s1 * 2];
        float2 h2 = *(const float2*)&g_hw2[s2 * 2];
        float2 h3 = *(const float2*)&g_hw2[s3 * 2];
        a0 = fmaf(d0, h0.x, a0); a1 = fmaf(d0, h0.y, a1);
        a0 = fmaf(d1, h1.x, a0); a1 = fmaf(d1, h1.y, a1);
        a0 = fmaf(d2, h2.x, a0); a1 = fmaf(d2, h2.y, a1);
        a0 = fmaf(d3, h3.x, a0); a1 = fmaf(d3, h3.y, a1);
    }
    for (; p < p1; p++) {
        int s = g_srcv[p];
        float ds = g_dinv[s];
        float2 hs = *(const float2*)&g_hw2[s * 2];
        a0 = fmaf(ds, hs.x, a0);
        a1 = fmaf(ds, hs.y, a1);
    }
    float e0 = fmaf(di, a0, b2[0]);
    float e1 = fmaf(di, a1, b2[1]);
    emb[i * 2 + 0] = e0;
    emb[i * 2 + 1] = e1;
    g_sq[i] = e0 * e0 + e1 * e1;
}

// ---------------- q matrix: q = 1/(1 + 0.5*dist), streaming float4 stores ----------------
#define TJ 1024
#define TI 16

__device__ __forceinline__ float qval(float d2) {
    float d2c = fmaxf(d2, 1e-30f);
    float dist = d2c * rsqrtf(d2c);
    return __fdividef(1.0f, fmaf(0.5f, dist, 1.0f));
}

__global__ __launch_bounds__(256) void k_q(const float* __restrict__ emb,
                                           float* __restrict__ q) {
    __shared__ float sx[TJ], sy[TJ], ss[TJ];
    int j0 = blockIdx.x * TJ;
    int i0 = blockIdx.y * TI;
    int t = threadIdx.x;
#pragma unroll
    for (int v = 0; v < 4; v++) {
        int jl = t + v * 256;
        int jj = j0 + jl;
        if (jj < NN) {
            sx[jl] = emb[jj * 2 + 0];
            sy[jl] = emb[jj * 2 + 1];
            ss[jl] = g_sq[jj];
        }
    }
    __syncthreads();
    int jl = t * 4;
    int j = j0 + jl;
    if (j >= NN) return;
    float x0 = sx[jl], x1 = sx[jl + 1], x2 = sx[jl + 2], x3 = sx[jl + 3];
    float y0 = sy[jl], y1 = sy[jl + 1], y2 = sy[jl + 2], y3 = sy[jl + 3];
    float s0 = ss[jl], s1 = ss[jl + 1], s2 = ss[jl + 2], s3 = ss[jl + 3];
#pragma unroll
    for (int r = 0; r < TI; r++) {
        int i = i0 + r;
        float ex = emb[i * 2 + 0];
        float ey = emb[i * 2 + 1];
        float si = g_sq[i];
        float4 o;
        o.x = qval(si + s0 - 2.0f * fmaf(ex, x0, ey * y0));
        o.y = qval(si + s1 - 2.0f * fmaf(ex, x1, ey * y1));
        o.z = qval(si + s2 - 2.0f * fmaf(ex, x2, ey * y2));
        o.w = qval(si + s3 - 2.0f * fmaf(ex, x3, ey * y3));
        __stcs((float4*)(q + (size_t)i * NN + j), o);
    }
}

// ---------------- launch: fork CSR branch onto a second stream ----------------
extern "C" void kernel_launch(void* const* d_in, const int* in_sizes, int n_in,
                              void* d_out, int out_size) {
    const float* features = (const float*)d_in[0];
    const int*   ei       = (const int*)d_in[1];
    const float* W1       = (const float*)d_in[2];
    const float* b1       = (const float*)d_in[3];
    const float* W2       = (const float*)d_in[4];
    const float* b2       = (const float*)d_in[5];
    float* out = (float*)d_out;
    float* emb = out;                 // [NN, 2]
    float* q   = out + NN * OUTD;     // [NN, NN]

    cudaFuncSetAttribute(k_gemm_mma, cudaFuncAttributeMaxDynamicSharedMemorySize, GEMM_SMEM);

    cudaStream_t s1 = 0;
    cudaEvent_t e0 = 0, e1 = 0;
    bool forked =
        cudaStreamCreateWithFlags(&s1, cudaStreamNonBlocking) == cudaSuccess &&
        cudaEventCreateWithFlags(&e0, cudaEventDisableTiming) == cudaSuccess &&
        cudaEventCreateWithFlags(&e1, cudaEventDisableTiming) == cudaSuccess;

    int csrGrid = (EE / 4 + 255) / 256;
    dim3 gg(HID / 128, (NN + 63) / 64);  // (2, 157) = 314 CTAs

    if (forked && cudaEventRecord(e0, 0) == cudaSuccess &&
        cudaStreamWaitEvent(s1, e0, 0) == cudaSuccess) {
        // side branch: CSR build
        k_count<<<csrGrid, 256, 0, s1>>>(ei);
        k_scan<<<1, 256, 0, s1>>>();
        k_scatter<<<csrGrid, 256, 0, s1>>>(ei);
        cudaEventRecord(e1, s1);
        // main branch: fp16 conversion + GEMM (overlaps CSR)
        k_cvtW<<<dim3(KPAD / 32, HID / 32), dim3(32, 8)>>>(W1);
        k_cvtA<<<NN * 128 / 256, 256>>>(features);
        k_gemm_mma<<<gg, 256, GEMM_SMEM>>>();
        cudaStreamWaitEvent(0, e1, 0);   // join before agg1
    } else {
        // serial fallback
        k_cvtW<<<dim3(KPAD / 32, HID / 32), dim3(32, 8)>>>(W1);
        k_cvtA<<<NN * 128 / 256, 256>>>(features);
        k_count<<<csrGrid, 256>>>(ei);
        k_scan<<<1, 256>>>();
        k_gemm_mma<<<gg, 256, GEMM_SMEM>>>();
        k_scatter<<<csrGrid, 256>>>(ei);
    }

    k_agg1<<<(NN * 32 + 255) / 256, 256>>>(b1, W2);
    k_agg2<<<(NN + 255) / 256, 256>>>(b2, emb);

    dim3 gq((NN + TJ - 1) / TJ, NN / TI);
    k_q<<<gq, 256>>>(emb, q);
}